// round 14
// baseline (speedup 1.0000x reference)
#include <cuda_runtime.h>
#include <cuda_bf16.h>
#include <math.h>
#include <stdint.h>

#define S_LEN 2048
#define HID   4096
#define NH    32
#define DQK   192
#define DV    128

// ---------------------------------------------------------------------------
// scratch (device globals; no allocations allowed)
// ---------------------------------------------------------------------------
__device__ float g_qc [2048*4096];
__device__ float g_qr [2048*2048];
__device__ float g_kc [2048*4096];
__device__ float g_kr [2048*128];
__device__ float g_bkr[128];

__device__ __align__(16) __nv_bfloat16 g_h_hi [2048*4096], g_h_lo [2048*4096];
__device__ __align__(16) __nv_bfloat16 g_cq_hi[2048*1536], g_cq_lo[2048*1536];
__device__ __align__(16) __nv_bfloat16 g_ckv_hi[2048*512], g_ckv_lo[2048*512];
__device__ __align__(16) __nv_bfloat16 g_ao_hi[2048*4096], g_ao_lo[2048*4096];
__device__ __align__(16) __nv_bfloat16 g_Wqlr_hi[1536*4096], g_Wqlr_lo[1536*4096];
__device__ __align__(16) __nv_bfloat16 g_Wqc_hi [4096*1536], g_Wqc_lo [4096*1536];
__device__ __align__(16) __nv_bfloat16 g_Wqr_hi [2048*1536], g_Wqr_lo [2048*1536];
__device__ __align__(16) __nv_bfloat16 g_Wkv_hi [512*4096],  g_Wkv_lo [512*4096];
__device__ __align__(16) __nv_bfloat16 g_Wkc_hi [4096*512],  g_Wkc_lo [4096*512];
__device__ __align__(16) __nv_bfloat16 g_Wv_hi  [4096*512],  g_Wv_lo  [4096*512];
__device__ __align__(16) __nv_bfloat16 g_Wo_hi  [4096*4096], g_Wo_lo  [4096*4096];
__device__ __align__(16) __nv_bfloat16 g_Wkr_hi [128*4096],  g_Wkr_lo [128*4096];

__device__ __align__(16) __nv_bfloat16 g_qhi[2048*32*192], g_qlo[2048*32*192];
__device__ __align__(16) __nv_bfloat16 g_khi[2048*32*192], g_klo[2048*32*192];
__device__ __align__(16) __nv_bfloat16 g_vhi[2048*4096],   g_vlo[2048*4096];

// ---------------------------------------------------------------------------
// small PTX helpers
// ---------------------------------------------------------------------------
__device__ __forceinline__ uint32_t smem_u32(const void* p) {
    uint32_t a;
    asm("{ .reg .u64 t; cvta.to.shared.u64 t, %1; cvt.u32.u64 %0, t; }" : "=r"(a) : "l"(p));
    return a;
}
#define CP_ASYNC16(dst_u32, src_ptr) \
    asm volatile("cp.async.cg.shared.global [%0], [%1], 16;" \
                 :: "r"(dst_u32), "l"(__cvta_generic_to_global(src_ptr)) : "memory")
#define CP_COMMIT() asm volatile("cp.async.commit_group;" ::: "memory")
#define CP_WAIT(n)  asm volatile("cp.async.wait_group %0;" :: "n"(n) : "memory")

__device__ __forceinline__ void ldmx4(uint32_t& r0, uint32_t& r1, uint32_t& r2, uint32_t& r3,
                                      uint32_t addr) {
    asm volatile("ldmatrix.sync.aligned.m8n8.x4.shared.b16 {%0,%1,%2,%3}, [%4];"
                 : "=r"(r0), "=r"(r1), "=r"(r2), "=r"(r3) : "r"(addr));
}
__device__ __forceinline__ void ldmx4t(uint32_t& r0, uint32_t& r1, uint32_t& r2, uint32_t& r3,
                                       uint32_t addr) {
    asm volatile("ldmatrix.sync.aligned.m8n8.x4.trans.shared.b16 {%0,%1,%2,%3}, [%4];"
                 : "=r"(r0), "=r"(r1), "=r"(r2), "=r"(r3) : "r"(addr));
}
__device__ __forceinline__ void mma_bf16(float* d, const uint32_t* a, const uint32_t* b) {
    asm volatile("mma.sync.aligned.m16n8k16.row.col.f32.bf16.bf16.f32 "
                 "{%0,%1,%2,%3}, {%4,%5,%6,%7}, {%8,%9}, {%0,%1,%2,%3};"
                 : "+f"(d[0]), "+f"(d[1]), "+f"(d[2]), "+f"(d[3])
                 : "r"(a[0]), "r"(a[1]), "r"(a[2]), "r"(a[3]), "r"(b[0]), "r"(b[1]));
}
__device__ __forceinline__ uint32_t pack_hi(float a, float b) {
    __nv_bfloat16 ha = __float2bfloat16(a), hb = __float2bfloat16(b);
    return (uint32_t)__bfloat16_as_ushort(ha) | ((uint32_t)__bfloat16_as_ushort(hb) << 16);
}
__device__ __forceinline__ uint32_t pack_lo(float a, float b) {
    __nv_bfloat16 ha = __float2bfloat16(a), hb = __float2bfloat16(b);
    __nv_bfloat16 la = __float2bfloat16(a - __bfloat162float(ha));
    __nv_bfloat16 lb = __float2bfloat16(b - __bfloat162float(hb));
    return (uint32_t)__bfloat16_as_ushort(la) | ((uint32_t)__bfloat16_as_ushort(lb) << 16);
}

// ---------------------------------------------------------------------------
// mega split: 2x float4 per thread, 128-bit stores
// ---------------------------------------------------------------------------
struct SJob { const float* x; __nv_bfloat16* hi; __nv_bfloat16* lo; int n8; int blk0; };
struct SJobs { SJob j[8]; };

__global__ void multi_split_kernel(SJobs jobs) {
    int b = blockIdx.x;
    int ji = 0;
#pragma unroll
    for (int t = 1; t < 8; t++)
        if (b >= jobs.j[t].blk0) ji = t;
    const SJob jb = jobs.j[ji];
    int i = (b - jb.blk0) * 256 + threadIdx.x;
    if (i >= jb.n8) return;
    float4 v0 = ((const float4*)jb.x)[i * 2];
    float4 v1 = ((const float4*)jb.x)[i * 2 + 1];
    uint4 H, L;
    H.x = pack_hi(v0.x, v0.y); H.y = pack_hi(v0.z, v0.w);
    H.z = pack_hi(v1.x, v1.y); H.w = pack_hi(v1.z, v1.w);
    L.x = pack_lo(v0.x, v0.y); L.y = pack_lo(v0.z, v0.w);
    L.z = pack_lo(v1.x, v1.y); L.w = pack_lo(v1.z, v1.w);
    ((uint4*)jb.hi)[i] = H;
    ((uint4*)jb.lo)[i] = L;
}

__global__ void pad_krope_kernel(const float* __restrict__ W,
                                 __nv_bfloat16* __restrict__ hi,
                                 __nv_bfloat16* __restrict__ lo,
                                 const float* __restrict__ b,
                                 float* __restrict__ bp) {
    int i = blockIdx.x * blockDim.x + threadIdx.x;
    if (i < 128) bp[i] = (i < 64) ? b[i] : 0.f;
    if (i >= 128 * 4096) return;
    int r = i >> 12;
    float v = (r < 64) ? W[(size_t)r * 4096 + (i & 4095)] : 0.f;
    __nv_bfloat16 h = __float2bfloat16(v);
    hi[i] = h;
    lo[i] = __float2bfloat16(v - __bfloat162float(h));
}

// ---------------------------------------------------------------------------
// batched GEMM (unchanged from R13 passing version)
// ---------------------------------------------------------------------------
#define OA_HI 0
#define OA_LO 8192
#define OW_HI 16384
#define OW_LO 24576
#define ST_BUF 32768
#define G_SMEM (3 * ST_BUF)

__device__ __forceinline__ uint32_t swz64(int r, int c) {
    return (uint32_t)(r * 64 + ((c ^ ((r >> 1) & 3)) << 4));
}

struct GJob {
    const __nv_bfloat16 *Ahi, *Alo, *Whi, *Wlo;
    const float* bias;
    float* Cf;
    __nv_bfloat16 *Chi, *Clo;
    int N, K, blk0, pad_;
};
struct GJobs { GJob j[4]; };

__global__ void __launch_bounds__(128)
mma_gemm6(GJobs jobs) {
    extern __shared__ char gsm[];
    const uint32_t s0 = smem_u32(gsm);
    const int tid = threadIdx.x, wid = tid >> 5, lane = tid & 31;
    const int warp_m = wid >> 1, warp_n = wid & 1;

    int bx = blockIdx.x;
    int ji = 0;
#pragma unroll
    for (int t = 1; t < 4; t++)
        if (bx >= jobs.j[t].blk0) ji = t;
    const GJob jb = jobs.j[ji];
    const int col0 = (bx - jb.blk0) * 128;
    const int row0 = blockIdx.y * 128;
    const int K = jb.K, N = jb.N;

    const int a_row = (lane & 7) + ((lane >> 3) & 1) * 8;
    const int b_row = (lane & 7) + (lane >> 4) * 8;
    const int a_c   = (lane >> 4);
    const int b_c   = ((lane >> 3) & 1);

    uint32_t adA[4][2], adW[4][2];
#pragma unroll
    for (int mt = 0; mt < 4; mt++) {
        int rr = warp_m * 64 + mt * 16 + a_row;
#pragma unroll
        for (int ks = 0; ks < 2; ks++)
            adA[mt][ks] = OA_HI + swz64(rr, ks * 2 + a_c);
    }
#pragma unroll
    for (int np = 0; np < 4; np++) {
        int rr = warp_n * 64 + np * 16 + b_row;
#pragma unroll
        for (int ks = 0; ks < 2; ks++)
            adW[np][ks] = OW_HI + swz64(rr, ks * 2 + b_c);
    }

    const int kc = K >> 5;

    float acc[4][8][4];
#pragma unroll
    for (int mt = 0; mt < 4; mt++)
#pragma unroll
        for (int nt = 0; nt < 8; nt++)
#pragma unroll
            for (int e = 0; e < 4; e++) acc[mt][nt][e] = 0.f;

    auto load_chunk = [&](int c, int st) {
        const int kk = c << 5;
        const uint32_t base = s0 + st * ST_BUF;
#pragma unroll
        for (int i = 0; i < 4; i++) {
            int idx = tid + i * 128;
            int r = idx >> 2, cb = idx & 3;
            uint32_t doff = swz64(r, cb);
            size_t src = (size_t)(row0 + r) * K + kk + cb * 8;
            CP_ASYNC16(base + OA_HI + doff, jb.Ahi + src);
            CP_ASYNC16(base + OA_LO + doff, jb.Alo + src);
        }
#pragma unroll
        for (int i = 0; i < 4; i++) {
            int idx = tid + i * 128;
            int r = idx >> 2, cb = idx & 3;
            uint32_t doff = swz64(r, cb);
            size_t src = (size_t)(col0 + r) * K + kk + cb * 8;
            CP_ASYNC16(base + OW_HI + doff, jb.Whi + src);
            CP_ASYNC16(base + OW_LO + doff, jb.Wlo + src);
        }
        CP_COMMIT();
    };

    load_chunk(0, 0);
    load_chunk(1, 1);

    int st = 0, ls = 2;
    for (int c = 0; c < kc; c++) {
        if (c + 1 < kc) { CP_WAIT(1); } else { CP_WAIT(0); }
        __syncthreads();
        const uint32_t base = s0 + st * ST_BUF;

        // ks = 0 (critical path first)
        {
            uint32_t ah[4][4], al[4][4];
#pragma unroll
            for (int mt = 0; mt < 4; mt++) {
                uint32_t ra = base + adA[mt][0];
                ldmx4(ah[mt][0], ah[mt][1], ah[mt][2], ah[mt][3], ra);
                ldmx4(al[mt][0], al[mt][1], al[mt][2], al[mt][3], ra + (OA_LO - OA_HI));
            }
#pragma unroll
            for (int np = 0; np < 4; np++) {
                uint32_t bh[4], bl[4];
                uint32_t rb = base + adW[np][0];
                ldmx4(bh[0], bh[1], bh[2], bh[3], rb);
                ldmx4(bl[0], bl[1], bl[2], bl[3], rb + (OW_LO - OW_HI));
#pragma unroll
                for (int j = 0; j < 2; j++) {
                    uint32_t b2h[2] = { bh[j * 2], bh[j * 2 + 1] };
                    uint32_t b2l[2] = { bl[j * 2], bl[j * 2 + 1] };
                    const int nt = np * 2 + j;
#pragma unroll
                    for (int mt = 0; mt < 4; mt++) mma_bf16(acc[mt][nt], ah[mt], b2h);
#pragma unroll
                    for (int mt = 0; mt < 4; mt++) mma_bf16(acc[mt][nt], al[mt], b2h);
#pragma unroll
                    for (int mt = 0; mt < 4; mt++) mma_bf16(acc[mt][nt], ah[mt], b2l);
                }
            }
        }

        if (c + 2 < kc) load_chunk(c + 2, ls);

        // ks = 1
        {
            uint32_t ah[4][4], al[4][4];
#pragma unroll
            for (int mt = 0; mt < 4; mt++) {
                uint32_t ra = base + adA[mt][1];
                ldmx4(ah[mt][0], ah[mt][1], ah[mt][2], ah[mt][3], ra);
                ldmx4(al[mt][0], al[mt][1], al[mt][2], al[mt][3], ra + (OA_LO - OA_HI));
            }
#pragma unroll
            for (int np = 0; np < 4; np++) {
                uint32_t bh[4], bl[4];
                uint32_t rb = base + adW[np][1];
                ldmx4(bh[0], bh[1], bh[2], bh[3], rb);
                ldmx4(bl[0], bl[1], bl[2], bl[3], rb + (OW_LO - OW_HI));
#pragma unroll
                for (int j = 0; j < 2; j++) {
                    uint32_t b2h[2] = { bh[j * 2], bh[j * 2 + 1] };
                    uint32_t b2l[2] = { bl[j * 2], bl[j * 2 + 1] };
                    const int nt = np * 2 + j;
#pragma unroll
                    for (int mt = 0; mt < 4; mt++) mma_bf16(acc[mt][nt], ah[mt], b2h);
#pragma unroll
                    for (int mt = 0; mt < 4; mt++) mma_bf16(acc[mt][nt], al[mt], b2h);
#pragma unroll
                    for (int mt = 0; mt < 4; mt++) mma_bf16(acc[mt][nt], ah[mt], b2l);
                }
            }
        }
        st = (st == 2) ? 0 : st + 1;
        ls = (ls == 2) ? 0 : ls + 1;
    }

    const int rbase = row0 + warp_m * 64 + (lane >> 2);
    const int cbase = col0 + warp_n * 64 + (lane & 3) * 2;
#pragma unroll
    for (int mt = 0; mt < 4; mt++) {
#pragma unroll
        for (int nt = 0; nt < 8; nt++) {
            const int cc = cbase + nt * 8;
            const float b0 = jb.bias[cc], b1 = jb.bias[cc + 1];
            const int r0 = rbase + mt * 16;
            float v0 = acc[mt][nt][0] + b0, v1 = acc[mt][nt][1] + b1;
            float v2 = acc[mt][nt][2] + b0, v3 = acc[mt][nt][3] + b1;
            if (jb.Cf) {
                *(float2*)&jb.Cf[(size_t)r0 * N + cc] = make_float2(v0, v1);
                *(float2*)&jb.Cf[(size_t)(r0 + 8) * N + cc] = make_float2(v2, v3);
            }
            if (jb.Chi) {
                *(uint32_t*)&jb.Chi[(size_t)r0 * N + cc]       = pack_hi(v0, v1);
                *(uint32_t*)&jb.Chi[(size_t)(r0 + 8) * N + cc] = pack_hi(v2, v3);
                *(uint32_t*)&jb.Clo[(size_t)r0 * N + cc]       = pack_lo(v0, v1);
                *(uint32_t*)&jb.Clo[(size_t)(r0 + 8) * N + cc] = pack_lo(v2, v3);
            }
        }
    }
}

// ---------------- merged concat + inline RoPE + RMSnorm (q and k) ------------
__global__ void fuse_qk_kernel(const float* __restrict__ qc,
                               const float* __restrict__ qr,
                               const float* __restrict__ kc,
                               const float* __restrict__ kr,
                               __nv_bfloat16* __restrict__ qh,
                               __nv_bfloat16* __restrict__ ql,
                               __nv_bfloat16* __restrict__ kh,
                               __nv_bfloat16* __restrict__ kl) {
    const bool is_k = blockIdx.x >= 8192;
    const int  bx   = is_k ? blockIdx.x - 8192 : blockIdx.x;
    const int gw   = ((bx * blockDim.x) + threadIdx.x) >> 5;
    const int lane = threadIdx.x & 31;
    const int s = gw >> 5, h = gw & 31;
    float vals[6]; float ss = 0.f;
#pragma unroll
    for (int t = 0; t < 6; t++) {
        int d = lane + 32 * t;
        float x;
        if (d < 128) {
            x = is_k ? kc[(size_t)s * HID + h * 128 + d]
                     : qc[(size_t)s * HID + h * 128 + d];
        } else if (!is_k) {
            int j = h * 64 + (d - 128);
            int base = (j < 1024) ? j : j - 1024;
            float ex  = (float)(2 * base) / 2048.0f;
            float inv = 1.0f / powf(10000.0f, ex);
            float sn, c;
            sincosf((float)s * inv, &sn, &c);
            if (j < 1024)
                x = qr[(size_t)s * 2048 + j] * c - qr[(size_t)s * 2048 + j + 1024] * sn;
            else
                x = qr[(size_t)s * 2048 + j] * c + qr[(size_t)s * 2048 + base] * sn;
        } else {
            int j = d - 128;
            int base = (j < 32) ? j : j - 32;
            float ex  = (float)(2 * base) / 64.0f;
            float inv = 1.0f / powf(10000.0f, ex);
            float sn, c;
            sincosf((float)s * inv, &sn, &c);
            if (j < 32)
                x = kr[(size_t)s * 128 + j] * c - kr[(size_t)s * 128 + j + 32] * sn;
            else
                x = kr[(size_t)s * 128 + j] * c + kr[(size_t)s * 128 + base] * sn;
        }
        vals[t] = x; ss += x * x;
    }
#pragma unroll
    for (int o = 16; o; o >>= 1) ss += __shfl_xor_sync(0xffffffffu, ss, o);
    float r = rsqrtf(ss * (1.f / 192.f) + 1.1920929e-7f);
    __nv_bfloat16* dh = is_k ? kh : qh;
    __nv_bfloat16* dl = is_k ? kl : ql;
#pragma unroll
    for (int t = 0; t < 6; t++) {
        float x = vals[t] * r;
        __nv_bfloat16 hb = __float2bfloat16(x);
        size_t o_ = ((size_t)s * NH + h) * DQK + lane + 32 * t;
        dh[o_] = hb;
        dl[o_] = __float2bfloat16(x - __bfloat162float(hb));
    }
}

// ---------------------------------------------------------------------------
// flash attention (unchanged from R13 passing version)
// ---------------------------------------------------------------------------
#define OQH 0
#define OQL (64*400)
#define OKH (2*64*400)
#define OKL (OKH + 32*400)
#define OVB (OKL + 32*400)
#define VHALF (32*272)
#define VBUF (2*VHALF)
#define ATT_SMEM (OVB + 2*VBUF)

__global__ void __launch_bounds__(128, 2)
attn_mma_kernel(const __nv_bfloat16* __restrict__ qhi, const __nv_bfloat16* __restrict__ qlo,
                const __nv_bfloat16* __restrict__ khi, const __nv_bfloat16* __restrict__ klo,
                const __nv_bfloat16* __restrict__ vhi, const __nv_bfloat16* __restrict__ vlo,
                const float* __restrict__ mask,
                __nv_bfloat16* __restrict__ aoh, __nv_bfloat16* __restrict__ aol) {
    extern __shared__ char smraw[];
    const uint32_t s0 = smem_u32(smraw);
    const int h = blockIdx.y, q0 = blockIdx.x * 64;
    const int tid = threadIdx.x, wid = tid >> 5, lane = tid & 31;

    for (int i = tid; i < 1536; i += 128) {
        int r = i / 24, cb = i % 24;
        size_t src = ((size_t)(q0 + r) * NH + h) * DQK + cb * 8;
        CP_ASYNC16(s0 + OQH + r * 400 + cb * 16, qhi + src);
        CP_ASYNC16(s0 + OQL + r * 400 + cb * 16, qlo + src);
    }
    CP_COMMIT();

    auto load_k = [&](int k0) {
        for (int i = tid; i < 768; i += 128) {
            int r = i / 24, cb = i % 24;
            size_t src = ((size_t)(k0 + r) * NH + h) * DQK + cb * 8;
            CP_ASYNC16(s0 + OKH + r * 400 + cb * 16, khi + src);
            CP_ASYNC16(s0 + OKL + r * 400 + cb * 16, klo + src);
        }
        CP_COMMIT();
    };
    auto load_v = [&](int k0, int buf) {
        const uint32_t vb = s0 + OVB + buf * VBUF;
        for (int i = tid; i < 512; i += 128) {
            int r = i / 16, cb = i % 16;
            size_t src = (size_t)(k0 + r) * HID + h * DV + cb * 8;
            CP_ASYNC16(vb + r * 272 + cb * 16, vhi + src);
            CP_ASYNC16(vb + VHALF + r * 272 + cb * 16, vlo + src);
        }
        CP_COMMIT();
    };
    load_k(0);
    load_v(0, 0);

    const float scale = 1.0f / sqrtf(192.0f);
    float m0 = -1e30f, m1 = -1e30f, l0 = 0.f, l1 = 0.f;
    float acc[16][4];
#pragma unroll
    for (int nt = 0; nt < 16; nt++)
#pragma unroll
        for (int e = 0; e < 4; e++) acc[nt][e] = 0.f;

    const int a_r  = (lane & 7) + ((lane >> 3) & 1) * 8;
    const int a_k  = (lane >> 4) * 8;
    const int bk_r = (lane & 7) + (lane >> 4) * 8;
    const int bk_k = ((lane >> 3) & 1) * 8;
    const int prow  = lane >> 2;
    const int pcol2 = (lane & 3) * 2;
    const int rg0 = q0 + wid * 16 + prow;

    for (int c = 0; c < 64; c++) {
        const int k0 = c * 32;
        CP_WAIT(0);
        __syncthreads();

        float mk[4][4];
#pragma unroll
        for (int nt = 0; nt < 4; nt++) {
            int col = k0 + nt * 8 + pcol2;
            float2 m0v = *(const float2*)&mask[(size_t)rg0 * S_LEN + col];
            float2 m1v = *(const float2*)&mask[(size_t)(rg0 + 8) * S_LEN + col];
            mk[nt][0] = m0v.x; mk[nt][1] = m0v.y;
            mk[nt][2] = m1v.x; mk[nt][3] = m1v.y;
        }

        float sacc[4][4];
#pragma unroll
        for (int nt = 0; nt < 4; nt++)
#pragma unroll
            for (int e = 0; e < 4; e++) sacc[nt][e] = 0.f;

#pragma unroll
        for (int kt = 0; kt < 12; kt++) {
            uint32_t ah[4], al[4];
            ldmx4(ah[0], ah[1], ah[2], ah[3],
                  s0 + OQH + (wid * 16 + a_r) * 400 + (kt * 16 + a_k) * 2);
            ldmx4(al[0], al[1], al[2], al[3],
                  s0 + OQL + (wid * 16 + a_r) * 400 + (kt * 16 + a_k) * 2);
            uint32_t bh[2][4], bl[2][4];
#pragma unroll
            for (int n2 = 0; n2 < 2; n2++) {
                uint32_t rb = (n2 * 16 + bk_r) * 400 + (kt * 16 + bk_k) * 2;
                ldmx4(bh[n2][0], bh[n2][1], bh[n2][2], bh[n2][3], s0 + OKH + rb);
                ldmx4(bl[n2][0], bl[n2][1], bl[n2][2], bl[n2][3], s0 + OKL + rb);
            }
#pragma unroll
            for (int n2 = 0; n2 < 2; n2++) {
                mma_bf16(sacc[n2 * 2],     ah, &bh[n2][0]);
                mma_bf16(sacc[n2 * 2 + 1], ah, &bh[n2][2]);
            }
#pragma unroll
            for (int n2 = 0; n2 < 2; n2++) {
                mma_bf16(sacc[n2 * 2],     al, &bh[n2][0]);
                mma_bf16(sacc[n2 * 2 + 1], al, &bh[n2][2]);
            }
#pragma unroll
            for (int n2 = 0; n2 < 2; n2++) {
                mma_bf16(sacc[n2 * 2],     ah, &bl[n2][0]);
                mma_bf16(sacc[n2 * 2 + 1], ah, &bl[n2][2]);
            }
            if (kt == 0 && c + 1 < 64) load_v(k0 + 32, (c + 1) & 1);
        }
        __syncthreads();
        if (c + 1 < 64) load_k(k0 + 32);

        float mx0 = -1e30f, mx1 = -1e30f;
#pragma unroll
        for (int nt = 0; nt < 4; nt++) {
            sacc[nt][0] = sacc[nt][0] * scale + mk[nt][0];
            sacc[nt][1] = sacc[nt][1] * scale + mk[nt][1];
            sacc[nt][2] = sacc[nt][2] * scale + mk[nt][2];
            sacc[nt][3] = sacc[nt][3] * scale + mk[nt][3];
            mx0 = fmaxf(mx0, fmaxf(sacc[nt][0], sacc[nt][1]));
            mx1 = fmaxf(mx1, fmaxf(sacc[nt][2], sacc[nt][3]));
        }
        mx0 = fmaxf(mx0, __shfl_xor_sync(0xffffffffu, mx0, 1));
        mx0 = fmaxf(mx0, __shfl_xor_sync(0xffffffffu, mx0, 2));
        mx1 = fmaxf(mx1, __shfl_xor_sync(0xffffffffu, mx1, 1));
        mx1 = fmaxf(mx1, __shfl_xor_sync(0xffffffffu, mx1, 2));
        float mn0 = fmaxf(m0, mx0), mn1 = fmaxf(m1, mx1);
        float al0 = __expf(m0 - mn0), al1 = __expf(m1 - mn1);
        m0 = mn0; m1 = mn1;

        uint32_t pfh[2][4], pfl[2][4];
        float ps0 = 0.f, ps1 = 0.f;
#pragma unroll
        for (int nt = 0; nt < 4; nt++) {
            float p00 = __expf(sacc[nt][0] - mn0), p01 = __expf(sacc[nt][1] - mn0);
            float p10 = __expf(sacc[nt][2] - mn1), p11 = __expf(sacc[nt][3] - mn1);
            ps0 += p00 + p01; ps1 += p10 + p11;
            const int kt = nt >> 1, sl = (nt & 1) * 2;
            pfh[kt][sl + 0] = pack_hi(p00, p01);
            pfh[kt][sl + 1] = pack_hi(p10, p11);
            pfl[kt][sl + 0] = pack_lo(p00, p01);
            pfl[kt][sl + 1] = pack_lo(p10, p11);
        }
        ps0 += __shfl_xor_sync(0xffffffffu, ps0, 1);
        ps0 += __shfl_xor_sync(0xffffffffu, ps0, 2);
        ps1 += __shfl_xor_sync(0xffffffffu, ps1, 1);
        ps1 += __shfl_xor_sync(0xffffffffu, ps1, 2);
        l0 = al0 * l0 + ps0;
        l1 = al1 * l1 + ps1;
#pragma unroll
        for (int nt = 0; nt < 16; nt++) {
            acc[nt][0] *= al0; acc[nt][1] *= al0;
            acc[nt][2] *= al1; acc[nt][3] *= al1;
        }

        const uint32_t vb = s0 + OVB + (c & 1) * VBUF;
#pragma unroll
        for (int kt = 0; kt < 2; kt++) {
#pragma unroll
            for (int n2 = 0; n2 < 8; n2++) {
                uint32_t vh[4], vl[4];
                uint32_t rv = (kt * 16 + a_r) * 272 + (n2 * 16 + a_k) * 2;
                ldmx4t(vh[0], vh[1], vh[2], vh[3], vb + rv);
                ldmx4t(vl[0], vl[1], vl[2], vl[3], vb + VHALF + rv);
                uint32_t vh0[2] = { vh[0], vh[1] }, vh1[2] = { vh[2], vh[3] };
                uint32_t vl0[2] = { vl[0], vl[1] }, vl1[2] = { vl[2], vl[3] };
                mma_bf16(acc[n2 * 2],     pfh[kt], vh0);
                mma_bf16(acc[n2 * 2 + 1], pfh[kt], vh1);
                mma_bf16(acc[n2 * 2],     pfl[kt], vh0);
                mma_bf16(acc[n2 * 2 + 1], pfl[kt], vh1);
                mma_bf16(acc[n2 * 2],     pfh[kt], vl0);
                mma_bf16(acc[n2 * 2 + 1], pfh[kt], vl1);
            }
        }
    }

    const float i0 = 1.f / l0, i1 = 1.f / l1;
    const int orow = q0 + wid * 16 + prow;
#pragma unroll
    for (int nt = 0; nt < 16; nt++) {
        int col = h * DV + nt * 8 + pcol2;
        float v0 = acc[nt][0] * i0, v1 = acc[nt][1] * i0;
        float v2 = acc[nt][2] * i1, v3 = acc[nt][3] * i1;
        *(uint32_t*)&aoh[(size_t)orow * HID + col]       = pack_hi(v0, v1);
        *(uint32_t*)&aoh[(size_t)(orow + 8) * HID + col] = pack_hi(v2, v3);
        *(uint32_t*)&aol[(size_t)orow * HID + col]       = pack_lo(v0, v1);
        *(uint32_t*)&aol[(size_t)(orow + 8) * HID + col] = pack_lo(v2, v3);
    }
}

// ---------------------------------------------------------------------------
// launcher (stream-forked: splitB overlaps G1)
// ---------------------------------------------------------------------------
extern "C" void kernel_launch(void* const* d_in, const int* in_sizes, int n_in,
                              void* d_out, int out_size) {
    const float* hidden  = (const float*)d_in[0];
    const float* mask    = (const float*)d_in[1];
    const float* Wq_lr   = (const float*)d_in[2];
    const float* bq_lr   = (const float*)d_in[3];
    const float* Wq_rope = (const float*)d_in[4];
    const float* bq_rope = (const float*)d_in[5];
    const float* Wq_c    = (const float*)d_in[6];
    const float* bq_c    = (const float*)d_in[7];
    const float* Wkv     = (const float*)d_in[8];
    const float* bkv     = (const float*)d_in[9];
    const float* Wk_rope = (const float*)d_in[10];
    const float* bk_rope = (const float*)d_in[11];
    const float* Wk_c    = (const float*)d_in[12];
    const float* bk_c    = (const float*)d_in[13];
    const float* Wv      = (const float*)d_in[14];
    const float* bv      = (const float*)d_in[15];
    const float* Wo      = (const float*)d_in[16];
    const float* bo      = (const float*)d_in[17];
    float* out = (float*)d_out;

    float *qc, *qr, *kc, *kr, *bkr;
    cudaGetSymbolAddress((void**)&qc,  g_qc);
    cudaGetSymbolAddress((void**)&qr,  g_qr);
    cudaGetSymbolAddress((void**)&kc,  g_kc);
    cudaGetSymbolAddress((void**)&kr,  g_kr);
    cudaGetSymbolAddress((void**)&bkr, g_bkr);

    __nv_bfloat16 *h_hi, *h_lo, *cq_hi, *cq_lo, *ckv_hi, *ckv_lo, *ao_hi, *ao_lo;
    __nv_bfloat16 *Wqlr_hi, *Wqlr_lo, *Wqc_hi, *Wqc_lo, *Wqr_hi, *Wqr_lo;
    __nv_bfloat16 *Wkv_hi, *Wkv_lo, *Wkc_hi, *Wkc_lo, *Wv_hi, *Wv_lo, *Wo_hi, *Wo_lo;
    __nv_bfloat16 *Wkr_hi, *Wkr_lo, *qhi, *qlo, *khi, *klo, *vhi, *vlo;
    cudaGetSymbolAddress((void**)&h_hi,   g_h_hi);   cudaGetSymbolAddress((void**)&h_lo,   g_h_lo);
    cudaGetSymbolAddress((void**)&cq_hi,  g_cq_hi);  cudaGetSymbolAddress((void**)&cq_lo,  g_cq_lo);
    cudaGetSymbolAddress((void**)&ckv_hi, g_ckv_hi); cudaGetSymbolAddress((void**)&ckv_lo, g_ckv_lo);
    cudaGetSymbolAddress((void**)&ao_hi,  g_ao_hi);  cudaGetSymbolAddress((void**)&ao_lo,  g_ao_lo);
    cudaGetSymbolAddress((void**)&Wqlr_hi, g_Wqlr_hi); cudaGetSymbolAddress((void**)&Wqlr_lo, g_Wqlr_lo);
    cudaGetSymbolAddress((void**)&Wqc_hi,  g_Wqc_hi);  cudaGetSymbolAddress((void**)&Wqc_lo,  g_Wqc_lo);
    cudaGetSymbolAddress((void**)&Wqr_hi,  g_Wqr_hi);  cudaGetSymbolAddress((void**)&Wqr_lo,  g_Wqr_lo);
    cudaGetSymbolAddress((void**)&Wkv_hi,  g_Wkv_hi);  cudaGetSymbolAddress((void**)&Wkv_lo,  g_Wkv_lo);
    cudaGetSymbolAddress((void**)&Wkc_hi,  g_Wkc_hi);  cudaGetSymbolAddress((void**)&Wkc_lo,  g_Wkc_lo);
    cudaGetSymbolAddress((void**)&Wv_hi,   g_Wv_hi);   cudaGetSymbolAddress((void**)&Wv_lo,   g_Wv_lo);
    cudaGetSymbolAddress((void**)&Wo_hi,   g_Wo_hi);   cudaGetSymbolAddress((void**)&Wo_lo,   g_Wo_lo);
    cudaGetSymbolAddress((void**)&Wkr_hi,  g_Wkr_hi);  cudaGetSymbolAddress((void**)&Wkr_lo,  g_Wkr_lo);
    cudaGetSymbolAddress((void**)&qhi, g_qhi); cudaGetSymbolAddress((void**)&qlo, g_qlo);
    cudaGetSymbolAddress((void**)&khi, g_khi); cudaGetSymbolAddress((void**)&klo, g_klo);
    cudaGetSymbolAddress((void**)&vhi, g_vhi); cudaGetSymbolAddress((void**)&vlo, g_vlo);

    cudaFuncSetAttribute(mma_gemm6, cudaFuncAttributeMaxDynamicSharedMemorySize, G_SMEM);
    cudaFuncSetAttribute(attn_mma_kernel, cudaFuncAttributeMaxDynamicSharedMemorySize, ATT_SMEM);

    const int NONE = 0x7FFFFFFF;

    // stream fork resources (host objects; no device memory)
    cudaStream_t s2;
    cudaStreamCreateWithFlags(&s2, cudaStreamNonBlocking);
    cudaEvent_t evFork, evJoin;
    cudaEventCreateWithFlags(&evFork, cudaEventDisableTiming);
    cudaEventCreateWithFlags(&evJoin, cudaEventDisableTiming);

    // ---- splitA (G1 inputs): hidden, Wq_lr, Wkv (default stream) ----
    {
        SJobs ja{};
        const float* srcs[3] = { hidden, Wq_lr, Wkv };
        __nv_bfloat16* his[3] = { h_hi, Wqlr_hi, Wkv_hi };
        __nv_bfloat16* los[3] = { h_lo, Wqlr_lo, Wkv_lo };
        int ns[3] = { 2048*4096, 1536*4096, 512*4096 };
        int blk = 0;
        for (int i = 0; i < 3; i++) {
            ja.j[i].x = srcs[i]; ja.j[i].hi = his[i]; ja.j[i].lo = los[i];
            ja.j[i].n8 = ns[i] / 8; ja.j[i].blk0 = blk;
            blk += (ja.j[i].n8 + 255) / 256;
        }
        for (int i = 3; i < 8; i++) { ja.j[i] = ja.j[0]; ja.j[i].blk0 = NONE; }
        multi_split_kernel<<<blk, 256>>>(ja);
    }
    pad_krope_kernel<<<(128 * 4096 + 255) / 256, 256>>>(Wk_rope, Wkr_hi, Wkr_lo, bk_rope, bkr);

    // ---- fork: splitB (G2G3/G4 weights) on s2, concurrent with G1 ----
    cudaEventRecord(evFork, 0);
    cudaStreamWaitEvent(s2, evFork, 0);
    {
        SJobs jbx{};
        const float* srcs[5] = { Wq_c, Wq_rope, Wk_c, Wv, Wo };
        __nv_bfloat16* his[5] = { Wqc_hi, Wqr_hi, Wkc_hi, Wv_hi, Wo_hi };
        __nv_bfloat16* los[5] = { Wqc_lo, Wqr_lo, Wkc_lo, Wv_lo, Wo_lo };
        int ns[5] = { 4096*1536, 2048*1536, 4096*512, 4096*512, 4096*4096 };
        int blk = 0;
        for (int i = 0; i < 5; i++) {
            jbx.j[i].x = srcs[i]; jbx.j[i].hi = his[i]; jbx.j[i].lo = los[i];
            jbx.j[i].n8 = ns[i] / 8; jbx.j[i].blk0 = blk;
            blk += (jbx.j[i].n8 + 255) / 256;
        }
        for (int i = 5; i < 8; i++) { jbx.j[i] = jbx.j[0]; jbx.j[i].blk0 = NONE; }
        multi_split_kernel<<<blk, 256, 0, s2>>>(jbx);
    }
    cudaEventRecord(evJoin, s2);

    // ---- G1 on default stream (overlaps splitB) ----
    {
        GJobs g{};
        g.j[0] = { h_hi, h_lo, Wqlr_hi, Wqlr_lo, bq_lr, nullptr, cq_hi, cq_lo, 1536, 4096, 0, 0 };
        g.j[1] = { h_hi, h_lo, Wkv_hi,  Wkv_lo,  bkv,   nullptr, ckv_hi, ckv_lo, 512, 4096, 12, 0 };
        g.j[2] = { h_hi, h_lo, Wkr_hi,  Wkr_lo,  bkr,   kr, nullptr, nullptr, 128, 4096, 16, 0 };
        g.j[3] = g.j[2]; g.j[3].blk0 = NONE;
        mma_gemm6<<<dim3(17, 16), 128, G_SMEM>>>(g);
    }

    // ---- join: G2G3 needs splitB outputs ----
    cudaStreamWaitEvent(0, evJoin, 0);
    {
        GJobs g{};
        g.j[0] = { cq_hi, cq_lo, Wqc_hi, Wqc_lo, bq_c,    qc, nullptr, nullptr, 4096, 1536, 0,  0 };
        g.j[1] = { cq_hi, cq_lo, Wqr_hi, Wqr_lo, bq_rope, qr, nullptr, nullptr, 2048, 1536, 32, 0 };
        g.j[2] = { ckv_hi, ckv_lo, Wkc_hi, Wkc_lo, bk_c,  kc, nullptr, nullptr, 4096, 512, 48, 0 };
        g.j[3] = { ckv_hi, ckv_lo, Wv_hi,  Wv_lo,  bv, nullptr, vhi, vlo,       4096, 512, 80, 0 };
        mma_gemm6<<<dim3(112, 16), 128, G_SMEM>>>(g);
    }

    fuse_qk_kernel<<<16384, 256>>>(qc, qr, kc, kr, qhi, qlo, khi, klo);

    attn_mma_kernel<<<dim3(S_LEN / 64, NH), 128, ATT_SMEM>>>(
        qhi, qlo, khi, klo, vhi, vlo, mask, ao_hi, ao_lo);

    // G4: out = ao @ Wo^T
    {
        GJobs g{};
        g.j[0] = { ao_hi, ao_lo, Wo_hi, Wo_lo, bo, out, nullptr, nullptr, 4096, 4096, 0, 0 };
        g.j[1] = g.j[0]; g.j[1].blk0 = NONE;
        g.j[2] = g.j[0]; g.j[2].blk0 = NONE;
        g.j[3] = g.j[0]; g.j[3].blk0 = NONE;
        mma_gemm6<<<dim3(32, 16), 128, G_SMEM>>>(g);
    }
}

// round 16
// speedup vs baseline: 1.0028x; 1.0028x over previous
#include <cuda_runtime.h>
#include <cuda_bf16.h>
#include <math.h>
#include <stdint.h>

#define S_LEN 2048
#define HID   4096
#define NH    32
#define DQK   192
#define DV    128

// ---------------------------------------------------------------------------
// scratch (device globals; no allocations allowed)
// ---------------------------------------------------------------------------
__device__ float g_qc [2048*4096];
__device__ float g_qr [2048*2048];
__device__ float g_kc [2048*4096];
__device__ float g_kr [2048*128];
__device__ float g_bkr[128];

__device__ __align__(16) __nv_bfloat16 g_h_hi [2048*4096], g_h_lo [2048*4096];
__device__ __align__(16) __nv_bfloat16 g_cq_hi[2048*1536], g_cq_lo[2048*1536];
__device__ __align__(16) __nv_bfloat16 g_ckv_hi[2048*512], g_ckv_lo[2048*512];
__device__ __align__(16) __nv_bfloat16 g_ao_hi[2048*4096], g_ao_lo[2048*4096];
__device__ __align__(16) __nv_bfloat16 g_Wqlr_hi[1536*4096], g_Wqlr_lo[1536*4096];
__device__ __align__(16) __nv_bfloat16 g_Wqc_hi [4096*1536], g_Wqc_lo [4096*1536];
__device__ __align__(16) __nv_bfloat16 g_Wqr_hi [2048*1536], g_Wqr_lo [2048*1536];
__device__ __align__(16) __nv_bfloat16 g_Wkv_hi [512*4096],  g_Wkv_lo [512*4096];
__device__ __align__(16) __nv_bfloat16 g_Wkc_hi [4096*512],  g_Wkc_lo [4096*512];
__device__ __align__(16) __nv_bfloat16 g_Wv_hi  [4096*512],  g_Wv_lo  [4096*512];
__device__ __align__(16) __nv_bfloat16 g_Wo_hi  [4096*4096], g_Wo_lo  [4096*4096];
__device__ __align__(16) __nv_bfloat16 g_Wkr_hi [128*4096],  g_Wkr_lo [128*4096];

__device__ __align__(16) __nv_bfloat16 g_qhi[2048*32*192], g_qlo[2048*32*192];
__device__ __align__(16) __nv_bfloat16 g_khi[2048*32*192], g_klo[2048*32*192];
__device__ __align__(16) __nv_bfloat16 g_vhi[2048*4096],   g_vlo[2048*4096];

// ---------------------------------------------------------------------------
// small PTX helpers
// ---------------------------------------------------------------------------
__device__ __forceinline__ uint32_t smem_u32(const void* p) {
    uint32_t a;
    asm("{ .reg .u64 t; cvta.to.shared.u64 t, %1; cvt.u32.u64 %0, t; }" : "=r"(a) : "l"(p));
    return a;
}
#define CP_ASYNC16(dst_u32, src_ptr) \
    asm volatile("cp.async.cg.shared.global [%0], [%1], 16;" \
                 :: "r"(dst_u32), "l"(__cvta_generic_to_global(src_ptr)) : "memory")
#define CP_COMMIT() asm volatile("cp.async.commit_group;" ::: "memory")
#define CP_WAIT(n)  asm volatile("cp.async.wait_group %0;" :: "n"(n) : "memory")

__device__ __forceinline__ void ldmx4(uint32_t& r0, uint32_t& r1, uint32_t& r2, uint32_t& r3,
                                      uint32_t addr) {
    asm volatile("ldmatrix.sync.aligned.m8n8.x4.shared.b16 {%0,%1,%2,%3}, [%4];"
                 : "=r"(r0), "=r"(r1), "=r"(r2), "=r"(r3) : "r"(addr));
}
__device__ __forceinline__ void ldmx4t(uint32_t& r0, uint32_t& r1, uint32_t& r2, uint32_t& r3,
                                       uint32_t addr) {
    asm volatile("ldmatrix.sync.aligned.m8n8.x4.trans.shared.b16 {%0,%1,%2,%3}, [%4];"
                 : "=r"(r0), "=r"(r1), "=r"(r2), "=r"(r3) : "r"(addr));
}
__device__ __forceinline__ void mma_bf16(float* d, const uint32_t* a, const uint32_t* b) {
    asm volatile("mma.sync.aligned.m16n8k16.row.col.f32.bf16.bf16.f32 "
                 "{%0,%1,%2,%3}, {%4,%5,%6,%7}, {%8,%9}, {%0,%1,%2,%3};"
                 : "+f"(d[0]), "+f"(d[1]), "+f"(d[2]), "+f"(d[3])
                 : "r"(a[0]), "r"(a[1]), "r"(a[2]), "r"(a[3]), "r"(b[0]), "r"(b[1]));
}
__device__ __forceinline__ uint32_t pack_hi(float a, float b) {
    __nv_bfloat16 ha = __float2bfloat16(a), hb = __float2bfloat16(b);
    return (uint32_t)__bfloat16_as_ushort(ha) | ((uint32_t)__bfloat16_as_ushort(hb) << 16);
}
__device__ __forceinline__ uint32_t pack_lo(float a, float b) {
    __nv_bfloat16 ha = __float2bfloat16(a), hb = __float2bfloat16(b);
    __nv_bfloat16 la = __float2bfloat16(a - __bfloat162float(ha));
    __nv_bfloat16 lb = __float2bfloat16(b - __bfloat162float(hb));
    return (uint32_t)__bfloat16_as_ushort(la) | ((uint32_t)__bfloat16_as_ushort(lb) << 16);
}

// ---------------------------------------------------------------------------
// mega split: 2x float4 per thread, 128-bit stores
// ---------------------------------------------------------------------------
struct SJob { const float* x; __nv_bfloat16* hi; __nv_bfloat16* lo; int n8; int blk0; };
struct SJobs { SJob j[8]; };

__global__ void multi_split_kernel(SJobs jobs) {
    int b = blockIdx.x;
    int ji = 0;
#pragma unroll
    for (int t = 1; t < 8; t++)
        if (b >= jobs.j[t].blk0) ji = t;
    const SJob jb = jobs.j[ji];
    int i = (b - jb.blk0) * 256 + threadIdx.x;
    if (i >= jb.n8) return;
    float4 v0 = ((const float4*)jb.x)[i * 2];
    float4 v1 = ((const float4*)jb.x)[i * 2 + 1];
    uint4 H, L;
    H.x = pack_hi(v0.x, v0.y); H.y = pack_hi(v0.z, v0.w);
    H.z = pack_hi(v1.x, v1.y); H.w = pack_hi(v1.z, v1.w);
    L.x = pack_lo(v0.x, v0.y); L.y = pack_lo(v0.z, v0.w);
    L.z = pack_lo(v1.x, v1.y); L.w = pack_lo(v1.z, v1.w);
    ((uint4*)jb.hi)[i] = H;
    ((uint4*)jb.lo)[i] = L;
}

__global__ void pad_krope_kernel(const float* __restrict__ W,
                                 __nv_bfloat16* __restrict__ hi,
                                 __nv_bfloat16* __restrict__ lo,
                                 const float* __restrict__ b,
                                 float* __restrict__ bp) {
    int i = blockIdx.x * blockDim.x + threadIdx.x;
    if (i < 128) bp[i] = (i < 64) ? b[i] : 0.f;
    if (i >= 128 * 4096) return;
    int r = i >> 12;
    float v = (r < 64) ? W[(size_t)r * 4096 + (i & 4095)] : 0.f;
    __nv_bfloat16 h = __float2bfloat16(v);
    hi[i] = h;
    lo[i] = __float2bfloat16(v - __bfloat162float(h));
}

// ---------------------------------------------------------------------------
// batched GEMM (unchanged from R13 passing version)
// ---------------------------------------------------------------------------
#define OA_HI 0
#define OA_LO 8192
#define OW_HI 16384
#define OW_LO 24576
#define ST_BUF 32768
#define G_SMEM (3 * ST_BUF)

__device__ __forceinline__ uint32_t swz64(int r, int c) {
    return (uint32_t)(r * 64 + ((c ^ ((r >> 1) & 3)) << 4));
}

struct GJob {
    const __nv_bfloat16 *Ahi, *Alo, *Whi, *Wlo;
    const float* bias;
    float* Cf;
    __nv_bfloat16 *Chi, *Clo;
    int N, K, blk0, pad_;
};
struct GJobs { GJob j[4]; };

__global__ void __launch_bounds__(128)
mma_gemm6(GJobs jobs) {
    extern __shared__ char gsm[];
    const uint32_t s0 = smem_u32(gsm);
    const int tid = threadIdx.x, wid = tid >> 5, lane = tid & 31;
    const int warp_m = wid >> 1, warp_n = wid & 1;

    int bx = blockIdx.x;
    int ji = 0;
#pragma unroll
    for (int t = 1; t < 4; t++)
        if (bx >= jobs.j[t].blk0) ji = t;
    const GJob jb = jobs.j[ji];
    const int col0 = (bx - jb.blk0) * 128;
    const int row0 = blockIdx.y * 128;
    const int K = jb.K, N = jb.N;

    const int a_row = (lane & 7) + ((lane >> 3) & 1) * 8;
    const int b_row = (lane & 7) + (lane >> 4) * 8;
    const int a_c   = (lane >> 4);
    const int b_c   = ((lane >> 3) & 1);

    uint32_t adA[4][2], adW[4][2];
#pragma unroll
    for (int mt = 0; mt < 4; mt++) {
        int rr = warp_m * 64 + mt * 16 + a_row;
#pragma unroll
        for (int ks = 0; ks < 2; ks++)
            adA[mt][ks] = OA_HI + swz64(rr, ks * 2 + a_c);
    }
#pragma unroll
    for (int np = 0; np < 4; np++) {
        int rr = warp_n * 64 + np * 16 + b_row;
#pragma unroll
        for (int ks = 0; ks < 2; ks++)
            adW[np][ks] = OW_HI + swz64(rr, ks * 2 + b_c);
    }

    const int kc = K >> 5;

    float acc[4][8][4];
#pragma unroll
    for (int mt = 0; mt < 4; mt++)
#pragma unroll
        for (int nt = 0; nt < 8; nt++)
#pragma unroll
            for (int e = 0; e < 4; e++) acc[mt][nt][e] = 0.f;

    auto load_chunk = [&](int c, int st) {
        const int kk = c << 5;
        const uint32_t base = s0 + st * ST_BUF;
#pragma unroll
        for (int i = 0; i < 4; i++) {
            int idx = tid + i * 128;
            int r = idx >> 2, cb = idx & 3;
            uint32_t doff = swz64(r, cb);
            size_t src = (size_t)(row0 + r) * K + kk + cb * 8;
            CP_ASYNC16(base + OA_HI + doff, jb.Ahi + src);
            CP_ASYNC16(base + OA_LO + doff, jb.Alo + src);
        }
#pragma unroll
        for (int i = 0; i < 4; i++) {
            int idx = tid + i * 128;
            int r = idx >> 2, cb = idx & 3;
            uint32_t doff = swz64(r, cb);
            size_t src = (size_t)(col0 + r) * K + kk + cb * 8;
            CP_ASYNC16(base + OW_HI + doff, jb.Whi + src);
            CP_ASYNC16(base + OW_LO + doff, jb.Wlo + src);
        }
        CP_COMMIT();
    };

    load_chunk(0, 0);
    load_chunk(1, 1);

    int st = 0, ls = 2;
    for (int c = 0; c < kc; c++) {
        if (c + 1 < kc) { CP_WAIT(1); } else { CP_WAIT(0); }
        __syncthreads();
        const uint32_t base = s0 + st * ST_BUF;

        // ks = 0 (critical path first)
        {
            uint32_t ah[4][4], al[4][4];
#pragma unroll
            for (int mt = 0; mt < 4; mt++) {
                uint32_t ra = base + adA[mt][0];
                ldmx4(ah[mt][0], ah[mt][1], ah[mt][2], ah[mt][3], ra);
                ldmx4(al[mt][0], al[mt][1], al[mt][2], al[mt][3], ra + (OA_LO - OA_HI));
            }
#pragma unroll
            for (int np = 0; np < 4; np++) {
                uint32_t bh[4], bl[4];
                uint32_t rb = base + adW[np][0];
                ldmx4(bh[0], bh[1], bh[2], bh[3], rb);
                ldmx4(bl[0], bl[1], bl[2], bl[3], rb + (OW_LO - OW_HI));
#pragma unroll
                for (int j = 0; j < 2; j++) {
                    uint32_t b2h[2] = { bh[j * 2], bh[j * 2 + 1] };
                    uint32_t b2l[2] = { bl[j * 2], bl[j * 2 + 1] };
                    const int nt = np * 2 + j;
#pragma unroll
                    for (int mt = 0; mt < 4; mt++) mma_bf16(acc[mt][nt], ah[mt], b2h);
#pragma unroll
                    for (int mt = 0; mt < 4; mt++) mma_bf16(acc[mt][nt], al[mt], b2h);
#pragma unroll
                    for (int mt = 0; mt < 4; mt++) mma_bf16(acc[mt][nt], ah[mt], b2l);
                }
            }
        }

        if (c + 2 < kc) load_chunk(c + 2, ls);

        // ks = 1
        {
            uint32_t ah[4][4], al[4][4];
#pragma unroll
            for (int mt = 0; mt < 4; mt++) {
                uint32_t ra = base + adA[mt][1];
                ldmx4(ah[mt][0], ah[mt][1], ah[mt][2], ah[mt][3], ra);
                ldmx4(al[mt][0], al[mt][1], al[mt][2], al[mt][3], ra + (OA_LO - OA_HI));
            }
#pragma unroll
            for (int np = 0; np < 4; np++) {
                uint32_t bh[4], bl[4];
                uint32_t rb = base + adW[np][1];
                ldmx4(bh[0], bh[1], bh[2], bh[3], rb);
                ldmx4(bl[0], bl[1], bl[2], bl[3], rb + (OW_LO - OW_HI));
#pragma unroll
                for (int j = 0; j < 2; j++) {
                    uint32_t b2h[2] = { bh[j * 2], bh[j * 2 + 1] };
                    uint32_t b2l[2] = { bl[j * 2], bl[j * 2 + 1] };
                    const int nt = np * 2 + j;
#pragma unroll
                    for (int mt = 0; mt < 4; mt++) mma_bf16(acc[mt][nt], ah[mt], b2h);
#pragma unroll
                    for (int mt = 0; mt < 4; mt++) mma_bf16(acc[mt][nt], al[mt], b2h);
#pragma unroll
                    for (int mt = 0; mt < 4; mt++) mma_bf16(acc[mt][nt], ah[mt], b2l);
                }
            }
        }
        st = (st == 2) ? 0 : st + 1;
        ls = (ls == 2) ? 0 : ls + 1;
    }

    const int rbase = row0 + warp_m * 64 + (lane >> 2);
    const int cbase = col0 + warp_n * 64 + (lane & 3) * 2;
#pragma unroll
    for (int mt = 0; mt < 4; mt++) {
#pragma unroll
        for (int nt = 0; nt < 8; nt++) {
            const int cc = cbase + nt * 8;
            const float b0 = jb.bias[cc], b1 = jb.bias[cc + 1];
            const int r0 = rbase + mt * 16;
            float v0 = acc[mt][nt][0] + b0, v1 = acc[mt][nt][1] + b1;
            float v2 = acc[mt][nt][2] + b0, v3 = acc[mt][nt][3] + b1;
            if (jb.Cf) {
                *(float2*)&jb.Cf[(size_t)r0 * N + cc] = make_float2(v0, v1);
                *(float2*)&jb.Cf[(size_t)(r0 + 8) * N + cc] = make_float2(v2, v3);
            }
            if (jb.Chi) {
                *(uint32_t*)&jb.Chi[(size_t)r0 * N + cc]       = pack_hi(v0, v1);
                *(uint32_t*)&jb.Chi[(size_t)(r0 + 8) * N + cc] = pack_hi(v2, v3);
                *(uint32_t*)&jb.Clo[(size_t)r0 * N + cc]       = pack_lo(v0, v1);
                *(uint32_t*)&jb.Clo[(size_t)(r0 + 8) * N + cc] = pack_lo(v2, v3);
            }
        }
    }
}

// ---------------- merged concat + inline RoPE + RMSnorm (q and k) ------------
// inv_freq via exp2f (MUFU-based): 1/10000^ex = 2^(-ex*log2(10000))
#define NLOG2_10000 (-13.287712379549449f)

__global__ void fuse_qk_kernel(const float* __restrict__ qc,
                               const float* __restrict__ qr,
                               const float* __restrict__ kc,
                               const float* __restrict__ kr,
                               __nv_bfloat16* __restrict__ qh,
                               __nv_bfloat16* __restrict__ ql,
                               __nv_bfloat16* __restrict__ kh,
                               __nv_bfloat16* __restrict__ kl) {
    const bool is_k = blockIdx.x >= 8192;
    const int  bx   = is_k ? blockIdx.x - 8192 : blockIdx.x;
    const int gw   = ((bx * blockDim.x) + threadIdx.x) >> 5;
    const int lane = threadIdx.x & 31;
    const int s = gw >> 5, h = gw & 31;
    float vals[6]; float ss = 0.f;
#pragma unroll
    for (int t = 0; t < 6; t++) {
        int d = lane + 32 * t;
        float x;
        if (d < 128) {
            x = is_k ? kc[(size_t)s * HID + h * 128 + d]
                     : qc[(size_t)s * HID + h * 128 + d];
        } else if (!is_k) {
            int j = h * 64 + (d - 128);
            int base = (j < 1024) ? j : j - 1024;
            float ex  = (float)(2 * base) / 2048.0f;
            float inv = exp2f(ex * NLOG2_10000);
            float sn, c;
            sincosf((float)s * inv, &sn, &c);
            if (j < 1024)
                x = qr[(size_t)s * 2048 + j] * c - qr[(size_t)s * 2048 + j + 1024] * sn;
            else
                x = qr[(size_t)s * 2048 + j] * c + qr[(size_t)s * 2048 + base] * sn;
        } else {
            int j = d - 128;
            int base = (j < 32) ? j : j - 32;
            float ex  = (float)(2 * base) / 64.0f;
            float inv = exp2f(ex * NLOG2_10000);
            float sn, c;
            sincosf((float)s * inv, &sn, &c);
            if (j < 32)
                x = kr[(size_t)s * 128 + j] * c - kr[(size_t)s * 128 + j + 32] * sn;
            else
                x = kr[(size_t)s * 128 + j] * c + kr[(size_t)s * 128 + base] * sn;
        }
        vals[t] = x; ss += x * x;
    }
#pragma unroll
    for (int o = 16; o; o >>= 1) ss += __shfl_xor_sync(0xffffffffu, ss, o);
    float r = rsqrtf(ss * (1.f / 192.f) + 1.1920929e-7f);
    __nv_bfloat16* dh = is_k ? kh : qh;
    __nv_bfloat16* dl = is_k ? kl : ql;
#pragma unroll
    for (int t = 0; t < 6; t++) {
        float x = vals[t] * r;
        __nv_bfloat16 hb = __float2bfloat16(x);
        size_t o_ = ((size_t)s * NH + h) * DQK + lane + 32 * t;
        dh[o_] = hb;
        dl[o_] = __float2bfloat16(x - __bfloat162float(hb));
    }
}

// ---------------------------------------------------------------------------
// flash attention (unchanged from R13 passing version)
// ---------------------------------------------------------------------------
#define OQH 0
#define OQL (64*400)
#define OKH (2*64*400)
#define OKL (OKH + 32*400)
#define OVB (OKL + 32*400)
#define VHALF (32*272)
#define VBUF (2*VHALF)
#define ATT_SMEM (OVB + 2*VBUF)

__global__ void __launch_bounds__(128, 2)
attn_mma_kernel(const __nv_bfloat16* __restrict__ qhi, const __nv_bfloat16* __restrict__ qlo,
                const __nv_bfloat16* __restrict__ khi, const __nv_bfloat16* __restrict__ klo,
                const __nv_bfloat16* __restrict__ vhi, const __nv_bfloat16* __restrict__ vlo,
                const float* __restrict__ mask,
                __nv_bfloat16* __restrict__ aoh, __nv_bfloat16* __restrict__ aol) {
    extern __shared__ char smraw[];
    const uint32_t s0 = smem_u32(smraw);
    const int h = blockIdx.y, q0 = blockIdx.x * 64;
    const int tid = threadIdx.x, wid = tid >> 5, lane = tid & 31;

    for (int i = tid; i < 1536; i += 128) {
        int r = i / 24, cb = i % 24;
        size_t src = ((size_t)(q0 + r) * NH + h) * DQK + cb * 8;
        CP_ASYNC16(s0 + OQH + r * 400 + cb * 16, qhi + src);
        CP_ASYNC16(s0 + OQL + r * 400 + cb * 16, qlo + src);
    }
    CP_COMMIT();

    auto load_k = [&](int k0) {
        for (int i = tid; i < 768; i += 128) {
            int r = i / 24, cb = i % 24;
            size_t src = ((size_t)(k0 + r) * NH + h) * DQK + cb * 8;
            CP_ASYNC16(s0 + OKH + r * 400 + cb * 16, khi + src);
            CP_ASYNC16(s0 + OKL + r * 400 + cb * 16, klo + src);
        }
        CP_COMMIT();
    };
    auto load_v = [&](int k0, int buf) {
        const uint32_t vb = s0 + OVB + buf * VBUF;
        for (int i = tid; i < 512; i += 128) {
            int r = i / 16, cb = i % 16;
            size_t src = (size_t)(k0 + r) * HID + h * DV + cb * 8;
            CP_ASYNC16(vb + r * 272 + cb * 16, vhi + src);
            CP_ASYNC16(vb + VHALF + r * 272 + cb * 16, vlo + src);
        }
        CP_COMMIT();
    };
    load_k(0);
    load_v(0, 0);

    const float scale = 1.0f / sqrtf(192.0f);
    float m0 = -1e30f, m1 = -1e30f, l0 = 0.f, l1 = 0.f;
    float acc[16][4];
#pragma unroll
    for (int nt = 0; nt < 16; nt++)
#pragma unroll
        for (int e = 0; e < 4; e++) acc[nt][e] = 0.f;

    const int a_r  = (lane & 7) + ((lane >> 3) & 1) * 8;
    const int a_k  = (lane >> 4) * 8;
    const int bk_r = (lane & 7) + (lane >> 4) * 8;
    const int bk_k = ((lane >> 3) & 1) * 8;
    const int prow  = lane >> 2;
    const int pcol2 = (lane & 3) * 2;
    const int rg0 = q0 + wid * 16 + prow;

    for (int c = 0; c < 64; c++) {
        const int k0 = c * 32;
        CP_WAIT(0);
        __syncthreads();

        float mk[4][4];
#pragma unroll
        for (int nt = 0; nt < 4; nt++) {
            int col = k0 + nt * 8 + pcol2;
            float2 m0v = *(const float2*)&mask[(size_t)rg0 * S_LEN + col];
            float2 m1v = *(const float2*)&mask[(size_t)(rg0 + 8) * S_LEN + col];
            mk[nt][0] = m0v.x; mk[nt][1] = m0v.y;
            mk[nt][2] = m1v.x; mk[nt][3] = m1v.y;
        }

        float sacc[4][4];
#pragma unroll
        for (int nt = 0; nt < 4; nt++)
#pragma unroll
            for (int e = 0; e < 4; e++) sacc[nt][e] = 0.f;

#pragma unroll
        for (int kt = 0; kt < 12; kt++) {
            uint32_t ah[4], al[4];
            ldmx4(ah[0], ah[1], ah[2], ah[3],
                  s0 + OQH + (wid * 16 + a_r) * 400 + (kt * 16 + a_k) * 2);
            ldmx4(al[0], al[1], al[2], al[3],
                  s0 + OQL + (wid * 16 + a_r) * 400 + (kt * 16 + a_k) * 2);
            uint32_t bh[2][4], bl[2][4];
#pragma unroll
            for (int n2 = 0; n2 < 2; n2++) {
                uint32_t rb = (n2 * 16 + bk_r) * 400 + (kt * 16 + bk_k) * 2;
                ldmx4(bh[n2][0], bh[n2][1], bh[n2][2], bh[n2][3], s0 + OKH + rb);
                ldmx4(bl[n2][0], bl[n2][1], bl[n2][2], bl[n2][3], s0 + OKL + rb);
            }
#pragma unroll
            for (int n2 = 0; n2 < 2; n2++) {
                mma_bf16(sacc[n2 * 2],     ah, &bh[n2][0]);
                mma_bf16(sacc[n2 * 2 + 1], ah, &bh[n2][2]);
            }
#pragma unroll
            for (int n2 = 0; n2 < 2; n2++) {
                mma_bf16(sacc[n2 * 2],     al, &bh[n2][0]);
                mma_bf16(sacc[n2 * 2 + 1], al, &bh[n2][2]);
            }
#pragma unroll
            for (int n2 = 0; n2 < 2; n2++) {
                mma_bf16(sacc[n2 * 2],     ah, &bl[n2][0]);
                mma_bf16(sacc[n2 * 2 + 1], ah, &bl[n2][2]);
            }
            if (kt == 0 && c + 1 < 64) load_v(k0 + 32, (c + 1) & 1);
        }
        __syncthreads();
        if (c + 1 < 64) load_k(k0 + 32);

        float mx0 = -1e30f, mx1 = -1e30f;
#pragma unroll
        for (int nt = 0; nt < 4; nt++) {
            sacc[nt][0] = sacc[nt][0] * scale + mk[nt][0];
            sacc[nt][1] = sacc[nt][1] * scale + mk[nt][1];
            sacc[nt][2] = sacc[nt][2] * scale + mk[nt][2];
            sacc[nt][3] = sacc[nt][3] * scale + mk[nt][3];
            mx0 = fmaxf(mx0, fmaxf(sacc[nt][0], sacc[nt][1]));
            mx1 = fmaxf(mx1, fmaxf(sacc[nt][2], sacc[nt][3]));
        }
        mx0 = fmaxf(mx0, __shfl_xor_sync(0xffffffffu, mx0, 1));
        mx0 = fmaxf(mx0, __shfl_xor_sync(0xffffffffu, mx0, 2));
        mx1 = fmaxf(mx1, __shfl_xor_sync(0xffffffffu, mx1, 1));
        mx1 = fmaxf(mx1, __shfl_xor_sync(0xffffffffu, mx1, 2));
        float mn0 = fmaxf(m0, mx0), mn1 = fmaxf(m1, mx1);
        float al0 = __expf(m0 - mn0), al1 = __expf(m1 - mn1);
        m0 = mn0; m1 = mn1;

        uint32_t pfh[2][4], pfl[2][4];
        float ps0 = 0.f, ps1 = 0.f;
#pragma unroll
        for (int nt = 0; nt < 4; nt++) {
            float p00 = __expf(sacc[nt][0] - mn0), p01 = __expf(sacc[nt][1] - mn0);
            float p10 = __expf(sacc[nt][2] - mn1), p11 = __expf(sacc[nt][3] - mn1);
            ps0 += p00 + p01; ps1 += p10 + p11;
            const int kt = nt >> 1, sl = (nt & 1) * 2;
            pfh[kt][sl + 0] = pack_hi(p00, p01);
            pfh[kt][sl + 1] = pack_hi(p10, p11);
            pfl[kt][sl + 0] = pack_lo(p00, p01);
            pfl[kt][sl + 1] = pack_lo(p10, p11);
        }
        ps0 += __shfl_xor_sync(0xffffffffu, ps0, 1);
        ps0 += __shfl_xor_sync(0xffffffffu, ps0, 2);
        ps1 += __shfl_xor_sync(0xffffffffu, ps1, 1);
        ps1 += __shfl_xor_sync(0xffffffffu, ps1, 2);
        l0 = al0 * l0 + ps0;
        l1 = al1 * l1 + ps1;
#pragma unroll
        for (int nt = 0; nt < 16; nt++) {
            acc[nt][0] *= al0; acc[nt][1] *= al0;
            acc[nt][2] *= al1; acc[nt][3] *= al1;
        }

        const uint32_t vb = s0 + OVB + (c & 1) * VBUF;
#pragma unroll
        for (int kt = 0; kt < 2; kt++) {
#pragma unroll
            for (int n2 = 0; n2 < 8; n2++) {
                uint32_t vh[4], vl[4];
                uint32_t rv = (kt * 16 + a_r) * 272 + (n2 * 16 + a_k) * 2;
                ldmx4t(vh[0], vh[1], vh[2], vh[3], vb + rv);
                ldmx4t(vl[0], vl[1], vl[2], vl[3], vb + VHALF + rv);
                uint32_t vh0[2] = { vh[0], vh[1] }, vh1[2] = { vh[2], vh[3] };
                uint32_t vl0[2] = { vl[0], vl[1] }, vl1[2] = { vl[2], vl[3] };
                mma_bf16(acc[n2 * 2],     pfh[kt], vh0);
                mma_bf16(acc[n2 * 2 + 1], pfh[kt], vh1);
                mma_bf16(acc[n2 * 2],     pfl[kt], vh0);
                mma_bf16(acc[n2 * 2 + 1], pfl[kt], vh1);
                mma_bf16(acc[n2 * 2],     pfh[kt], vl0);
                mma_bf16(acc[n2 * 2 + 1], pfh[kt], vl1);
            }
        }
    }

    const float i0 = 1.f / l0, i1 = 1.f / l1;
    const int orow = q0 + wid * 16 + prow;
#pragma unroll
    for (int nt = 0; nt < 16; nt++) {
        int col = h * DV + nt * 8 + pcol2;
        float v0 = acc[nt][0] * i0, v1 = acc[nt][1] * i0;
        float v2 = acc[nt][2] * i1, v3 = acc[nt][3] * i1;
        *(uint32_t*)&aoh[(size_t)orow * HID + col]       = pack_hi(v0, v1);
        *(uint32_t*)&aoh[(size_t)(orow + 8) * HID + col] = pack_hi(v2, v3);
        *(uint32_t*)&aol[(size_t)orow * HID + col]       = pack_lo(v0, v1);
        *(uint32_t*)&aol[(size_t)(orow + 8) * HID + col] = pack_lo(v2, v3);
    }
}

// ---------------------------------------------------------------------------
// launcher (single-stream, R13 topology; no stream/event objects)
// ---------------------------------------------------------------------------
extern "C" void kernel_launch(void* const* d_in, const int* in_sizes, int n_in,
                              void* d_out, int out_size) {
    const float* hidden  = (const float*)d_in[0];
    const float* mask    = (const float*)d_in[1];
    const float* Wq_lr   = (const float*)d_in[2];
    const float* bq_lr   = (const float*)d_in[3];
    const float* Wq_rope = (const float*)d_in[4];
    const float* bq_rope = (const float*)d_in[5];
    const float* Wq_c    = (const float*)d_in[6];
    const float* bq_c    = (const float*)d_in[7];
    const float* Wkv     = (const float*)d_in[8];
    const float* bkv     = (const float*)d_in[9];
    const float* Wk_rope = (const float*)d_in[10];
    const float* bk_rope = (const float*)d_in[11];
    const float* Wk_c    = (const float*)d_in[12];
    const float* bk_c    = (const float*)d_in[13];
    const float* Wv      = (const float*)d_in[14];
    const float* bv      = (const float*)d_in[15];
    const float* Wo      = (const float*)d_in[16];
    const float* bo      = (const float*)d_in[17];
    float* out = (float*)d_out;

    float *qc, *qr, *kc, *kr, *bkr;
    cudaGetSymbolAddress((void**)&qc,  g_qc);
    cudaGetSymbolAddress((void**)&qr,  g_qr);
    cudaGetSymbolAddress((void**)&kc,  g_kc);
    cudaGetSymbolAddress((void**)&kr,  g_kr);
    cudaGetSymbolAddress((void**)&bkr, g_bkr);

    __nv_bfloat16 *h_hi, *h_lo, *cq_hi, *cq_lo, *ckv_hi, *ckv_lo, *ao_hi, *ao_lo;
    __nv_bfloat16 *Wqlr_hi, *Wqlr_lo, *Wqc_hi, *Wqc_lo, *Wqr_hi, *Wqr_lo;
    __nv_bfloat16 *Wkv_hi, *Wkv_lo, *Wkc_hi, *Wkc_lo, *Wv_hi, *Wv_lo, *Wo_hi, *Wo_lo;
    __nv_bfloat16 *Wkr_hi, *Wkr_lo, *qhi, *qlo, *khi, *klo, *vhi, *vlo;
    cudaGetSymbolAddress((void**)&h_hi,   g_h_hi);   cudaGetSymbolAddress((void**)&h_lo,   g_h_lo);
    cudaGetSymbolAddress((void**)&cq_hi,  g_cq_hi);  cudaGetSymbolAddress((void**)&cq_lo,  g_cq_lo);
    cudaGetSymbolAddress((void**)&ckv_hi, g_ckv_hi); cudaGetSymbolAddress((void**)&ckv_lo, g_ckv_lo);
    cudaGetSymbolAddress((void**)&ao_hi,  g_ao_hi);  cudaGetSymbolAddress((void**)&ao_lo,  g_ao_lo);
    cudaGetSymbolAddress((void**)&Wqlr_hi, g_Wqlr_hi); cudaGetSymbolAddress((void**)&Wqlr_lo, g_Wqlr_lo);
    cudaGetSymbolAddress((void**)&Wqc_hi,  g_Wqc_hi);  cudaGetSymbolAddress((void**)&Wqc_lo,  g_Wqc_lo);
    cudaGetSymbolAddress((void**)&Wqr_hi,  g_Wqr_hi);  cudaGetSymbolAddress((void**)&Wqr_lo,  g_Wqr_lo);
    cudaGetSymbolAddress((void**)&Wkv_hi,  g_Wkv_hi);  cudaGetSymbolAddress((void**)&Wkv_lo,  g_Wkv_lo);
    cudaGetSymbolAddress((void**)&Wkc_hi,  g_Wkc_hi);  cudaGetSymbolAddress((void**)&Wkc_lo,  g_Wkc_lo);
    cudaGetSymbolAddress((void**)&Wv_hi,   g_Wv_hi);   cudaGetSymbolAddress((void**)&Wv_lo,   g_Wv_lo);
    cudaGetSymbolAddress((void**)&Wo_hi,   g_Wo_hi);   cudaGetSymbolAddress((void**)&Wo_lo,   g_Wo_lo);
    cudaGetSymbolAddress((void**)&Wkr_hi,  g_Wkr_hi);  cudaGetSymbolAddress((void**)&Wkr_lo,  g_Wkr_lo);
    cudaGetSymbolAddress((void**)&qhi, g_qhi); cudaGetSymbolAddress((void**)&qlo, g_qlo);
    cudaGetSymbolAddress((void**)&khi, g_khi); cudaGetSymbolAddress((void**)&klo, g_klo);
    cudaGetSymbolAddress((void**)&vhi, g_vhi); cudaGetSymbolAddress((void**)&vlo, g_vlo);

    cudaFuncSetAttribute(mma_gemm6, cudaFuncAttributeMaxDynamicSharedMemorySize, G_SMEM);
    cudaFuncSetAttribute(attn_mma_kernel, cudaFuncAttributeMaxDynamicSharedMemorySize, ATT_SMEM);

    const int NONE = 0x7FFFFFFF;

    SJobs jobs;
    const float* srcs[8] = { hidden, Wq_lr, Wq_c, Wq_rope, Wkv, Wk_c, Wv, Wo };
    __nv_bfloat16* his[8] = { h_hi, Wqlr_hi, Wqc_hi, Wqr_hi, Wkv_hi, Wkc_hi, Wv_hi, Wo_hi };
    __nv_bfloat16* los[8] = { h_lo, Wqlr_lo, Wqc_lo, Wqr_lo, Wkv_lo, Wkc_lo, Wv_lo, Wo_lo };
    int ns[8] = { 2048*4096, 1536*4096, 4096*1536, 2048*1536,
                  512*4096, 4096*512, 4096*512, 4096*4096 };
    int blk = 0;
    for (int i = 0; i < 8; i++) {
        jobs.j[i].x = srcs[i]; jobs.j[i].hi = his[i]; jobs.j[i].lo = los[i];
        jobs.j[i].n8 = ns[i] / 8; jobs.j[i].blk0 = blk;
        blk += (jobs.j[i].n8 + 255) / 256;
    }
    multi_split_kernel<<<blk, 256>>>(jobs);
    pad_krope_kernel<<<(128 * 4096 + 255) / 256, 256>>>(Wk_rope, Wkr_hi, Wkr_lo, bk_rope, bkr);

    // G1: A = hidden (K=4096): c_q, c_kv, k_rope
    {
        GJobs g{};
        g.j[0] = { h_hi, h_lo, Wqlr_hi, Wqlr_lo, bq_lr, nullptr, cq_hi, cq_lo, 1536, 4096, 0, 0 };
        g.j[1] = { h_hi, h_lo, Wkv_hi,  Wkv_lo,  bkv,   nullptr, ckv_hi, ckv_lo, 512, 4096, 12, 0 };
        g.j[2] = { h_hi, h_lo, Wkr_hi,  Wkr_lo,  bkr,   kr, nullptr, nullptr, 128, 4096, 16, 0 };
        g.j[3] = g.j[2]; g.j[3].blk0 = NONE;
        mma_gemm6<<<dim3(17, 16), 128, G_SMEM>>>(g);
    }
    // G2+G3
    {
        GJobs g{};
        g.j[0] = { cq_hi, cq_lo, Wqc_hi, Wqc_lo, bq_c,    qc, nullptr, nullptr, 4096, 1536, 0,  0 };
        g.j[1] = { cq_hi, cq_lo, Wqr_hi, Wqr_lo, bq_rope, qr, nullptr, nullptr, 2048, 1536, 32, 0 };
        g.j[2] = { ckv_hi, ckv_lo, Wkc_hi, Wkc_lo, bk_c,  kc, nullptr, nullptr, 4096, 512, 48, 0 };
        g.j[3] = { ckv_hi, ckv_lo, Wv_hi,  Wv_lo,  bv, nullptr, vhi, vlo,       4096, 512, 80, 0 };
        mma_gemm6<<<dim3(112, 16), 128, G_SMEM>>>(g);
    }

    fuse_qk_kernel<<<16384, 256>>>(qc, qr, kc, kr, qhi, qlo, khi, klo);

    attn_mma_kernel<<<dim3(S_LEN / 64, NH), 128, ATT_SMEM>>>(
        qhi, qlo, khi, klo, vhi, vlo, mask, ao_hi, ao_lo);

    // G4: out = ao @ Wo^T
    {
        GJobs g{};
        g.j[0] = { ao_hi, ao_lo, Wo_hi, Wo_lo, bo, out, nullptr, nullptr, 4096, 4096, 0, 0 };
        g.j[1] = g.j[0]; g.j[1].blk0 = NONE;
        g.j[2] = g.j[0]; g.j[2].blk0 = NONE;
        g.j[3] = g.j[0]; g.j[3].blk0 = NONE;
        mma_gemm6<<<dim3(32, 16), 128, G_SMEM>>>(g);
    }
}

// round 17
// speedup vs baseline: 1.0448x; 1.0419x over previous
#include <cuda_runtime.h>
#include <cuda_bf16.h>
#include <math.h>
#include <stdint.h>

#define S_LEN 2048
#define HID   4096
#define NH    32
#define DQK   192
#define DV    128

// ---------------------------------------------------------------------------
// scratch (device globals; no allocations allowed)
// ---------------------------------------------------------------------------
__device__ float g_qc [2048*4096];
__device__ float g_qr [2048*2048];
__device__ float g_kc [2048*4096];
__device__ float g_kr [2048*128];
__device__ float g_bkr[128];

__device__ __align__(16) __nv_bfloat16 g_h_hi [2048*4096], g_h_lo [2048*4096];
__device__ __align__(16) __nv_bfloat16 g_cq_hi[2048*1536], g_cq_lo[2048*1536];
__device__ __align__(16) __nv_bfloat16 g_ckv_hi[2048*512], g_ckv_lo[2048*512];
__device__ __align__(16) __nv_bfloat16 g_ao_hi[2048*4096], g_ao_lo[2048*4096];
__device__ __align__(16) __nv_bfloat16 g_Wqlr_hi[1536*4096], g_Wqlr_lo[1536*4096];
__device__ __align__(16) __nv_bfloat16 g_Wqc_hi [4096*1536], g_Wqc_lo [4096*1536];
__device__ __align__(16) __nv_bfloat16 g_Wqr_hi [2048*1536], g_Wqr_lo [2048*1536];
__device__ __align__(16) __nv_bfloat16 g_Wkv_hi [512*4096],  g_Wkv_lo [512*4096];
__device__ __align__(16) __nv_bfloat16 g_Wkc_hi [4096*512],  g_Wkc_lo [4096*512];
__device__ __align__(16) __nv_bfloat16 g_Wv_hi  [4096*512],  g_Wv_lo  [4096*512];
__device__ __align__(16) __nv_bfloat16 g_Wo_hi  [4096*4096], g_Wo_lo  [4096*4096];
__device__ __align__(16) __nv_bfloat16 g_Wkr_hi [128*4096],  g_Wkr_lo [128*4096];

__device__ __align__(16) __nv_bfloat16 g_qhi[2048*32*192], g_qlo[2048*32*192];
__device__ __align__(16) __nv_bfloat16 g_khi[2048*32*192], g_klo[2048*32*192];
__device__ __align__(16) __nv_bfloat16 g_vhi[2048*4096],   g_vlo[2048*4096];

// ---------------------------------------------------------------------------
// small PTX helpers
// ---------------------------------------------------------------------------
__device__ __forceinline__ uint32_t smem_u32(const void* p) {
    uint32_t a;
    asm("{ .reg .u64 t; cvta.to.shared.u64 t, %1; cvt.u32.u64 %0, t; }" : "=r"(a) : "l"(p));
    return a;
}
#define CP_ASYNC16(dst_u32, src_ptr) \
    asm volatile("cp.async.cg.shared.global [%0], [%1], 16;" \
                 :: "r"(dst_u32), "l"(__cvta_generic_to_global(src_ptr)) : "memory")
#define CP_COMMIT() asm volatile("cp.async.commit_group;" ::: "memory")
#define CP_WAIT(n)  asm volatile("cp.async.wait_group %0;" :: "n"(n) : "memory")

__device__ __forceinline__ void ldmx4(uint32_t& r0, uint32_t& r1, uint32_t& r2, uint32_t& r3,
                                      uint32_t addr) {
    asm volatile("ldmatrix.sync.aligned.m8n8.x4.shared.b16 {%0,%1,%2,%3}, [%4];"
                 : "=r"(r0), "=r"(r1), "=r"(r2), "=r"(r3) : "r"(addr));
}
__device__ __forceinline__ void ldmx4t(uint32_t& r0, uint32_t& r1, uint32_t& r2, uint32_t& r3,
                                       uint32_t addr) {
    asm volatile("ldmatrix.sync.aligned.m8n8.x4.trans.shared.b16 {%0,%1,%2,%3}, [%4];"
                 : "=r"(r0), "=r"(r1), "=r"(r2), "=r"(r3) : "r"(addr));
}
__device__ __forceinline__ void mma_bf16(float* d, const uint32_t* a, const uint32_t* b) {
    asm volatile("mma.sync.aligned.m16n8k16.row.col.f32.bf16.bf16.f32 "
                 "{%0,%1,%2,%3}, {%4,%5,%6,%7}, {%8,%9}, {%0,%1,%2,%3};"
                 : "+f"(d[0]), "+f"(d[1]), "+f"(d[2]), "+f"(d[3])
                 : "r"(a[0]), "r"(a[1]), "r"(a[2]), "r"(a[3]), "r"(b[0]), "r"(b[1]));
}

// packed fp32 pair -> bf16x2 hi (rn) and bf16x2 lo residual (rn).
// Element a lands in bits [0:16), b in [16:32) -- matches prior pack_hi/pack_lo.
__device__ __forceinline__ void split2(float a, float b, uint32_t& H, uint32_t& L) {
    asm("cvt.rn.bf16x2.f32 %0, %1, %2;" : "=r"(H) : "f"(b), "f"(a));
    float ha = __uint_as_float(H << 16);
    float hb = __uint_as_float(H & 0xffff0000u);
    float la = a - ha, lb = b - hb;
    asm("cvt.rn.bf16x2.f32 %0, %1, %2;" : "=r"(L) : "f"(lb), "f"(la));
}

// ---------------------------------------------------------------------------
// mega split: 2x float4 per thread, packed bf16x2 converts, 128-bit stores
// ---------------------------------------------------------------------------
struct SJob { const float* x; __nv_bfloat16* hi; __nv_bfloat16* lo; int n8; int blk0; };
struct SJobs { SJob j[8]; };

__global__ void multi_split_kernel(SJobs jobs) {
    int b = blockIdx.x;
    int ji = 0;
#pragma unroll
    for (int t = 1; t < 8; t++)
        if (b >= jobs.j[t].blk0) ji = t;
    const SJob jb = jobs.j[ji];
    int i = (b - jb.blk0) * 256 + threadIdx.x;
    if (i >= jb.n8) return;
    float4 v0 = ((const float4*)jb.x)[i * 2];
    float4 v1 = ((const float4*)jb.x)[i * 2 + 1];
    uint4 H, L;
    split2(v0.x, v0.y, H.x, L.x);
    split2(v0.z, v0.w, H.y, L.y);
    split2(v1.x, v1.y, H.z, L.z);
    split2(v1.z, v1.w, H.w, L.w);
    ((uint4*)jb.hi)[i] = H;
    ((uint4*)jb.lo)[i] = L;
}

__global__ void pad_krope_kernel(const float* __restrict__ W,
                                 __nv_bfloat16* __restrict__ hi,
                                 __nv_bfloat16* __restrict__ lo,
                                 const float* __restrict__ b,
                                 float* __restrict__ bp) {
    int i = blockIdx.x * blockDim.x + threadIdx.x;
    if (i < 128) bp[i] = (i < 64) ? b[i] : 0.f;
    if (i >= 128 * 4096) return;
    int r = i >> 12;
    float v = (r < 64) ? W[(size_t)r * 4096 + (i & 4095)] : 0.f;
    __nv_bfloat16 h = __float2bfloat16(v);
    hi[i] = h;
    lo[i] = __float2bfloat16(v - __bfloat162float(h));
}

// ---------------------------------------------------------------------------
// batched GEMM (R13 structure; epilogue uses split2)
// ---------------------------------------------------------------------------
#define OA_HI 0
#define OA_LO 8192
#define OW_HI 16384
#define OW_LO 24576
#define ST_BUF 32768
#define G_SMEM (3 * ST_BUF)

__device__ __forceinline__ uint32_t swz64(int r, int c) {
    return (uint32_t)(r * 64 + ((c ^ ((r >> 1) & 3)) << 4));
}

struct GJob {
    const __nv_bfloat16 *Ahi, *Alo, *Whi, *Wlo;
    const float* bias;
    float* Cf;
    __nv_bfloat16 *Chi, *Clo;
    int N, K, blk0, pad_;
};
struct GJobs { GJob j[4]; };

__global__ void __launch_bounds__(128)
mma_gemm6(GJobs jobs) {
    extern __shared__ char gsm[];
    const uint32_t s0 = smem_u32(gsm);
    const int tid = threadIdx.x, wid = tid >> 5, lane = tid & 31;
    const int warp_m = wid >> 1, warp_n = wid & 1;

    int bx = blockIdx.x;
    int ji = 0;
#pragma unroll
    for (int t = 1; t < 4; t++)
        if (bx >= jobs.j[t].blk0) ji = t;
    const GJob jb = jobs.j[ji];
    const int col0 = (bx - jb.blk0) * 128;
    const int row0 = blockIdx.y * 128;
    const int K = jb.K, N = jb.N;

    const int a_row = (lane & 7) + ((lane >> 3) & 1) * 8;
    const int b_row = (lane & 7) + (lane >> 4) * 8;
    const int a_c   = (lane >> 4);
    const int b_c   = ((lane >> 3) & 1);

    uint32_t adA[4][2], adW[4][2];
#pragma unroll
    for (int mt = 0; mt < 4; mt++) {
        int rr = warp_m * 64 + mt * 16 + a_row;
#pragma unroll
        for (int ks = 0; ks < 2; ks++)
            adA[mt][ks] = OA_HI + swz64(rr, ks * 2 + a_c);
    }
#pragma unroll
    for (int np = 0; np < 4; np++) {
        int rr = warp_n * 64 + np * 16 + b_row;
#pragma unroll
        for (int ks = 0; ks < 2; ks++)
            adW[np][ks] = OW_HI + swz64(rr, ks * 2 + b_c);
    }

    const int kc = K >> 5;

    float acc[4][8][4];
#pragma unroll
    for (int mt = 0; mt < 4; mt++)
#pragma unroll
        for (int nt = 0; nt < 8; nt++)
#pragma unroll
            for (int e = 0; e < 4; e++) acc[mt][nt][e] = 0.f;

    auto load_chunk = [&](int c, int st) {
        const int kk = c << 5;
        const uint32_t base = s0 + st * ST_BUF;
#pragma unroll
        for (int i = 0; i < 4; i++) {
            int idx = tid + i * 128;
            int r = idx >> 2, cb = idx & 3;
            uint32_t doff = swz64(r, cb);
            size_t src = (size_t)(row0 + r) * K + kk + cb * 8;
            CP_ASYNC16(base + OA_HI + doff, jb.Ahi + src);
            CP_ASYNC16(base + OA_LO + doff, jb.Alo + src);
        }
#pragma unroll
        for (int i = 0; i < 4; i++) {
            int idx = tid + i * 128;
            int r = idx >> 2, cb = idx & 3;
            uint32_t doff = swz64(r, cb);
            size_t src = (size_t)(col0 + r) * K + kk + cb * 8;
            CP_ASYNC16(base + OW_HI + doff, jb.Whi + src);
            CP_ASYNC16(base + OW_LO + doff, jb.Wlo + src);
        }
        CP_COMMIT();
    };

    load_chunk(0, 0);
    load_chunk(1, 1);

    int st = 0, ls = 2;
    for (int c = 0; c < kc; c++) {
        if (c + 1 < kc) { CP_WAIT(1); } else { CP_WAIT(0); }
        __syncthreads();
        const uint32_t base = s0 + st * ST_BUF;

        // ks = 0 (critical path first)
        {
            uint32_t ah[4][4], al[4][4];
#pragma unroll
            for (int mt = 0; mt < 4; mt++) {
                uint32_t ra = base + adA[mt][0];
                ldmx4(ah[mt][0], ah[mt][1], ah[mt][2], ah[mt][3], ra);
                ldmx4(al[mt][0], al[mt][1], al[mt][2], al[mt][3], ra + (OA_LO - OA_HI));
            }
#pragma unroll
            for (int np = 0; np < 4; np++) {
                uint32_t bh[4], bl[4];
                uint32_t rb = base + adW[np][0];
                ldmx4(bh[0], bh[1], bh[2], bh[3], rb);
                ldmx4(bl[0], bl[1], bl[2], bl[3], rb + (OW_LO - OW_HI));
#pragma unroll
                for (int j = 0; j < 2; j++) {
                    uint32_t b2h[2] = { bh[j * 2], bh[j * 2 + 1] };
                    uint32_t b2l[2] = { bl[j * 2], bl[j * 2 + 1] };
                    const int nt = np * 2 + j;
#pragma unroll
                    for (int mt = 0; mt < 4; mt++) mma_bf16(acc[mt][nt], ah[mt], b2h);
#pragma unroll
                    for (int mt = 0; mt < 4; mt++) mma_bf16(acc[mt][nt], al[mt], b2h);
#pragma unroll
                    for (int mt = 0; mt < 4; mt++) mma_bf16(acc[mt][nt], ah[mt], b2l);
                }
            }
        }

        if (c + 2 < kc) load_chunk(c + 2, ls);

        // ks = 1
        {
            uint32_t ah[4][4], al[4][4];
#pragma unroll
            for (int mt = 0; mt < 4; mt++) {
                uint32_t ra = base + adA[mt][1];
                ldmx4(ah[mt][0], ah[mt][1], ah[mt][2], ah[mt][3], ra);
                ldmx4(al[mt][0], al[mt][1], al[mt][2], al[mt][3], ra + (OA_LO - OA_HI));
            }
#pragma unroll
            for (int np = 0; np < 4; np++) {
                uint32_t bh[4], bl[4];
                uint32_t rb = base + adW[np][1];
                ldmx4(bh[0], bh[1], bh[2], bh[3], rb);
                ldmx4(bl[0], bl[1], bl[2], bl[3], rb + (OW_LO - OW_HI));
#pragma unroll
                for (int j = 0; j < 2; j++) {
                    uint32_t b2h[2] = { bh[j * 2], bh[j * 2 + 1] };
                    uint32_t b2l[2] = { bl[j * 2], bl[j * 2 + 1] };
                    const int nt = np * 2 + j;
#pragma unroll
                    for (int mt = 0; mt < 4; mt++) mma_bf16(acc[mt][nt], ah[mt], b2h);
#pragma unroll
                    for (int mt = 0; mt < 4; mt++) mma_bf16(acc[mt][nt], al[mt], b2h);
#pragma unroll
                    for (int mt = 0; mt < 4; mt++) mma_bf16(acc[mt][nt], ah[mt], b2l);
                }
            }
        }
        st = (st == 2) ? 0 : st + 1;
        ls = (ls == 2) ? 0 : ls + 1;
    }

    const int rbase = row0 + warp_m * 64 + (lane >> 2);
    const int cbase = col0 + warp_n * 64 + (lane & 3) * 2;
#pragma unroll
    for (int mt = 0; mt < 4; mt++) {
#pragma unroll
        for (int nt = 0; nt < 8; nt++) {
            const int cc = cbase + nt * 8;
            const float b0 = jb.bias[cc], b1 = jb.bias[cc + 1];
            const int r0 = rbase + mt * 16;
            float v0 = acc[mt][nt][0] + b0, v1 = acc[mt][nt][1] + b1;
            float v2 = acc[mt][nt][2] + b0, v3 = acc[mt][nt][3] + b1;
            if (jb.Cf) {
                *(float2*)&jb.Cf[(size_t)r0 * N + cc] = make_float2(v0, v1);
                *(float2*)&jb.Cf[(size_t)(r0 + 8) * N + cc] = make_float2(v2, v3);
            }
            if (jb.Chi) {
                uint32_t H0, L0, H1, L1;
                split2(v0, v1, H0, L0);
                split2(v2, v3, H1, L1);
                *(uint32_t*)&jb.Chi[(size_t)r0 * N + cc]       = H0;
                *(uint32_t*)&jb.Chi[(size_t)(r0 + 8) * N + cc] = H1;
                *(uint32_t*)&jb.Clo[(size_t)r0 * N + cc]       = L0;
                *(uint32_t*)&jb.Clo[(size_t)(r0 + 8) * N + cc] = L1;
            }
        }
    }
}

// ---------------- merged concat + inline RoPE + RMSnorm (q and k) ------------
#define NLOG2_10000 (-13.287712379549449f)

__global__ void fuse_qk_kernel(const float* __restrict__ qc,
                               const float* __restrict__ qr,
                               const float* __restrict__ kc,
                               const float* __restrict__ kr,
                               __nv_bfloat16* __restrict__ qh,
                               __nv_bfloat16* __restrict__ ql,
                               __nv_bfloat16* __restrict__ kh,
                               __nv_bfloat16* __restrict__ kl) {
    const bool is_k = blockIdx.x >= 8192;
    const int  bx   = is_k ? blockIdx.x - 8192 : blockIdx.x;
    const int gw   = ((bx * blockDim.x) + threadIdx.x) >> 5;
    const int lane = threadIdx.x & 31;
    const int s = gw >> 5, h = gw & 31;
    float vals[6]; float ss = 0.f;
#pragma unroll
    for (int t = 0; t < 6; t++) {
        int d = lane + 32 * t;
        float x;
        if (d < 128) {
            x = is_k ? kc[(size_t)s * HID + h * 128 + d]
                     : qc[(size_t)s * HID + h * 128 + d];
        } else if (!is_k) {
            int j = h * 64 + (d - 128);
            int base = (j < 1024) ? j : j - 1024;
            float ex  = (float)(2 * base) / 2048.0f;
            float inv = exp2f(ex * NLOG2_10000);
            float sn, c;
            sincosf((float)s * inv, &sn, &c);
            if (j < 1024)
                x = qr[(size_t)s * 2048 + j] * c - qr[(size_t)s * 2048 + j + 1024] * sn;
            else
                x = qr[(size_t)s * 2048 + j] * c + qr[(size_t)s * 2048 + base] * sn;
        } else {
            int j = d - 128;
            int base = (j < 32) ? j : j - 32;
            float ex  = (float)(2 * base) / 64.0f;
            float inv = exp2f(ex * NLOG2_10000);
            float sn, c;
            sincosf((float)s * inv, &sn, &c);
            if (j < 32)
                x = kr[(size_t)s * 128 + j] * c - kr[(size_t)s * 128 + j + 32] * sn;
            else
                x = kr[(size_t)s * 128 + j] * c + kr[(size_t)s * 128 + base] * sn;
        }
        vals[t] = x; ss += x * x;
    }
#pragma unroll
    for (int o = 16; o; o >>= 1) ss += __shfl_xor_sync(0xffffffffu, ss, o);
    float r = rsqrtf(ss * (1.f / 192.f) + 1.1920929e-7f);
    __nv_bfloat16* dh = is_k ? kh : qh;
    __nv_bfloat16* dl = is_k ? kl : ql;
#pragma unroll
    for (int t = 0; t < 6; t++) {
        float x = vals[t] * r;
        __nv_bfloat16 hb = __float2bfloat16(x);
        size_t o_ = ((size_t)s * NH + h) * DQK + lane + 32 * t;
        dh[o_] = hb;
        dl[o_] = __float2bfloat16(x - __bfloat162float(hb));
    }
}

// ---------------------------------------------------------------------------
// flash attention (R13 structure; split2 in softmax + epilogue)
// ---------------------------------------------------------------------------
#define OQH 0
#define OQL (64*400)
#define OKH (2*64*400)
#define OKL (OKH + 32*400)
#define OVB (OKL + 32*400)
#define VHALF (32*272)
#define VBUF (2*VHALF)
#define ATT_SMEM (OVB + 2*VBUF)

__global__ void __launch_bounds__(128, 2)
attn_mma_kernel(const __nv_bfloat16* __restrict__ qhi, const __nv_bfloat16* __restrict__ qlo,
                const __nv_bfloat16* __restrict__ khi, const __nv_bfloat16* __restrict__ klo,
                const __nv_bfloat16* __restrict__ vhi, const __nv_bfloat16* __restrict__ vlo,
                const float* __restrict__ mask,
                __nv_bfloat16* __restrict__ aoh, __nv_bfloat16* __restrict__ aol) {
    extern __shared__ char smraw[];
    const uint32_t s0 = smem_u32(smraw);
    const int h = blockIdx.y, q0 = blockIdx.x * 64;
    const int tid = threadIdx.x, wid = tid >> 5, lane = tid & 31;

    for (int i = tid; i < 1536; i += 128) {
        int r = i / 24, cb = i % 24;
        size_t src = ((size_t)(q0 + r) * NH + h) * DQK + cb * 8;
        CP_ASYNC16(s0 + OQH + r * 400 + cb * 16, qhi + src);
        CP_ASYNC16(s0 + OQL + r * 400 + cb * 16, qlo + src);
    }
    CP_COMMIT();

    auto load_k = [&](int k0) {
        for (int i = tid; i < 768; i += 128) {
            int r = i / 24, cb = i % 24;
            size_t src = ((size_t)(k0 + r) * NH + h) * DQK + cb * 8;
            CP_ASYNC16(s0 + OKH + r * 400 + cb * 16, khi + src);
            CP_ASYNC16(s0 + OKL + r * 400 + cb * 16, klo + src);
        }
        CP_COMMIT();
    };
    auto load_v = [&](int k0, int buf) {
        const uint32_t vb = s0 + OVB + buf * VBUF;
        for (int i = tid; i < 512; i += 128) {
            int r = i / 16, cb = i % 16;
            size_t src = (size_t)(k0 + r) * HID + h * DV + cb * 8;
            CP_ASYNC16(vb + r * 272 + cb * 16, vhi + src);
            CP_ASYNC16(vb + VHALF + r * 272 + cb * 16, vlo + src);
        }
        CP_COMMIT();
    };
    load_k(0);
    load_v(0, 0);

    const float scale = 1.0f / sqrtf(192.0f);
    float m0 = -1e30f, m1 = -1e30f, l0 = 0.f, l1 = 0.f;
    float acc[16][4];
#pragma unroll
    for (int nt = 0; nt < 16; nt++)
#pragma unroll
        for (int e = 0; e < 4; e++) acc[nt][e] = 0.f;

    const int a_r  = (lane & 7) + ((lane >> 3) & 1) * 8;
    const int a_k  = (lane >> 4) * 8;
    const int bk_r = (lane & 7) + (lane >> 4) * 8;
    const int bk_k = ((lane >> 3) & 1) * 8;
    const int prow  = lane >> 2;
    const int pcol2 = (lane & 3) * 2;
    const int rg0 = q0 + wid * 16 + prow;

    for (int c = 0; c < 64; c++) {
        const int k0 = c * 32;
        CP_WAIT(0);
        __syncthreads();

        float mk[4][4];
#pragma unroll
        for (int nt = 0; nt < 4; nt++) {
            int col = k0 + nt * 8 + pcol2;
            float2 m0v = *(const float2*)&mask[(size_t)rg0 * S_LEN + col];
            float2 m1v = *(const float2*)&mask[(size_t)(rg0 + 8) * S_LEN + col];
            mk[nt][0] = m0v.x; mk[nt][1] = m0v.y;
            mk[nt][2] = m1v.x; mk[nt][3] = m1v.y;
        }

        float sacc[4][4];
#pragma unroll
        for (int nt = 0; nt < 4; nt++)
#pragma unroll
            for (int e = 0; e < 4; e++) sacc[nt][e] = 0.f;

#pragma unroll
        for (int kt = 0; kt < 12; kt++) {
            uint32_t ah[4], al[4];
            ldmx4(ah[0], ah[1], ah[2], ah[3],
                  s0 + OQH + (wid * 16 + a_r) * 400 + (kt * 16 + a_k) * 2);
            ldmx4(al[0], al[1], al[2], al[3],
                  s0 + OQL + (wid * 16 + a_r) * 400 + (kt * 16 + a_k) * 2);
            uint32_t bh[2][4], bl[2][4];
#pragma unroll
            for (int n2 = 0; n2 < 2; n2++) {
                uint32_t rb = (n2 * 16 + bk_r) * 400 + (kt * 16 + bk_k) * 2;
                ldmx4(bh[n2][0], bh[n2][1], bh[n2][2], bh[n2][3], s0 + OKH + rb);
                ldmx4(bl[n2][0], bl[n2][1], bl[n2][2], bl[n2][3], s0 + OKL + rb);
            }
#pragma unroll
            for (int n2 = 0; n2 < 2; n2++) {
                mma_bf16(sacc[n2 * 2],     ah, &bh[n2][0]);
                mma_bf16(sacc[n2 * 2 + 1], ah, &bh[n2][2]);
            }
#pragma unroll
            for (int n2 = 0; n2 < 2; n2++) {
                mma_bf16(sacc[n2 * 2],     al, &bh[n2][0]);
                mma_bf16(sacc[n2 * 2 + 1], al, &bh[n2][2]);
            }
#pragma unroll
            for (int n2 = 0; n2 < 2; n2++) {
                mma_bf16(sacc[n2 * 2],     ah, &bl[n2][0]);
                mma_bf16(sacc[n2 * 2 + 1], ah, &bl[n2][2]);
            }
            if (kt == 0 && c + 1 < 64) load_v(k0 + 32, (c + 1) & 1);
        }
        __syncthreads();
        if (c + 1 < 64) load_k(k0 + 32);

        float mx0 = -1e30f, mx1 = -1e30f;
#pragma unroll
        for (int nt = 0; nt < 4; nt++) {
            sacc[nt][0] = sacc[nt][0] * scale + mk[nt][0];
            sacc[nt][1] = sacc[nt][1] * scale + mk[nt][1];
            sacc[nt][2] = sacc[nt][2] * scale + mk[nt][2];
            sacc[nt][3] = sacc[nt][3] * scale + mk[nt][3];
            mx0 = fmaxf(mx0, fmaxf(sacc[nt][0], sacc[nt][1]));
            mx1 = fmaxf(mx1, fmaxf(sacc[nt][2], sacc[nt][3]));
        }
        mx0 = fmaxf(mx0, __shfl_xor_sync(0xffffffffu, mx0, 1));
        mx0 = fmaxf(mx0, __shfl_xor_sync(0xffffffffu, mx0, 2));
        mx1 = fmaxf(mx1, __shfl_xor_sync(0xffffffffu, mx1, 1));
        mx1 = fmaxf(mx1, __shfl_xor_sync(0xffffffffu, mx1, 2));
        float mn0 = fmaxf(m0, mx0), mn1 = fmaxf(m1, mx1);
        float al0 = __expf(m0 - mn0), al1 = __expf(m1 - mn1);
        m0 = mn0; m1 = mn1;

        uint32_t pfh[2][4], pfl[2][4];
        float ps0 = 0.f, ps1 = 0.f;
#pragma unroll
        for (int nt = 0; nt < 4; nt++) {
            float p00 = __expf(sacc[nt][0] - mn0), p01 = __expf(sacc[nt][1] - mn0);
            float p10 = __expf(sacc[nt][2] - mn1), p11 = __expf(sacc[nt][3] - mn1);
            ps0 += p00 + p01; ps1 += p10 + p11;
            const int kt = nt >> 1, sl = (nt & 1) * 2;
            split2(p00, p01, pfh[kt][sl + 0], pfl[kt][sl + 0]);
            split2(p10, p11, pfh[kt][sl + 1], pfl[kt][sl + 1]);
        }
        ps0 += __shfl_xor_sync(0xffffffffu, ps0, 1);
        ps0 += __shfl_xor_sync(0xffffffffu, ps0, 2);
        ps1 += __shfl_xor_sync(0xffffffffu, ps1, 1);
        ps1 += __shfl_xor_sync(0xffffffffu, ps1, 2);
        l0 = al0 * l0 + ps0;
        l1 = al1 * l1 + ps1;
#pragma unroll
        for (int nt = 0; nt < 16; nt++) {
            acc[nt][0] *= al0; acc[nt][1] *= al0;
            acc[nt][2] *= al1; acc[nt][3] *= al1;
        }

        const uint32_t vb = s0 + OVB + (c & 1) * VBUF;
#pragma unroll
        for (int kt = 0; kt < 2; kt++) {
#pragma unroll
            for (int n2 = 0; n2 < 8; n2++) {
                uint32_t vh[4], vl[4];
                uint32_t rv = (kt * 16 + a_r) * 272 + (n2 * 16 + a_k) * 2;
                ldmx4t(vh[0], vh[1], vh[2], vh[3], vb + rv);
                ldmx4t(vl[0], vl[1], vl[2], vl[3], vb + VHALF + rv);
                uint32_t vh0[2] = { vh[0], vh[1] }, vh1[2] = { vh[2], vh[3] };
                uint32_t vl0[2] = { vl[0], vl[1] }, vl1[2] = { vl[2], vl[3] };
                mma_bf16(acc[n2 * 2],     pfh[kt], vh0);
                mma_bf16(acc[n2 * 2 + 1], pfh[kt], vh1);
                mma_bf16(acc[n2 * 2],     pfl[kt], vh0);
                mma_bf16(acc[n2 * 2 + 1], pfl[kt], vh1);
                mma_bf16(acc[n2 * 2],     pfh[kt], vl0);
                mma_bf16(acc[n2 * 2 + 1], pfh[kt], vl1);
            }
        }
    }

    const float i0 = 1.f / l0, i1 = 1.f / l1;
    const int orow = q0 + wid * 16 + prow;
#pragma unroll
    for (int nt = 0; nt < 16; nt++) {
        int col = h * DV + nt * 8 + pcol2;
        float v0 = acc[nt][0] * i0, v1 = acc[nt][1] * i0;
        float v2 = acc[nt][2] * i1, v3 = acc[nt][3] * i1;
        uint32_t H0, L0, H1, L1;
        split2(v0, v1, H0, L0);
        split2(v2, v3, H1, L1);
        *(uint32_t*)&aoh[(size_t)orow * HID + col]       = H0;
        *(uint32_t*)&aoh[(size_t)(orow + 8) * HID + col] = H1;
        *(uint32_t*)&aol[(size_t)orow * HID + col]       = L0;
        *(uint32_t*)&aol[(size_t)(orow + 8) * HID + col] = L1;
    }
}

// ---------------------------------------------------------------------------
// launcher (single-stream, R13 topology)
// ---------------------------------------------------------------------------
extern "C" void kernel_launch(void* const* d_in, const int* in_sizes, int n_in,
                              void* d_out, int out_size) {
    const float* hidden  = (const float*)d_in[0];
    const float* mask    = (const float*)d_in[1];
    const float* Wq_lr   = (const float*)d_in[2];
    const float* bq_lr   = (const float*)d_in[3];
    const float* Wq_rope = (const float*)d_in[4];
    const float* bq_rope = (const float*)d_in[5];
    const float* Wq_c    = (const float*)d_in[6];
    const float* bq_c    = (const float*)d_in[7];
    const float* Wkv     = (const float*)d_in[8];
    const float* bkv     = (const float*)d_in[9];
    const float* Wk_rope = (const float*)d_in[10];
    const float* bk_rope = (const float*)d_in[11];
    const float* Wk_c    = (const float*)d_in[12];
    const float* bk_c    = (const float*)d_in[13];
    const float* Wv      = (const float*)d_in[14];
    const float* bv      = (const float*)d_in[15];
    const float* Wo      = (const float*)d_in[16];
    const float* bo      = (const float*)d_in[17];
    float* out = (float*)d_out;

    float *qc, *qr, *kc, *kr, *bkr;
    cudaGetSymbolAddress((void**)&qc,  g_qc);
    cudaGetSymbolAddress((void**)&qr,  g_qr);
    cudaGetSymbolAddress((void**)&kc,  g_kc);
    cudaGetSymbolAddress((void**)&kr,  g_kr);
    cudaGetSymbolAddress((void**)&bkr, g_bkr);

    __nv_bfloat16 *h_hi, *h_lo, *cq_hi, *cq_lo, *ckv_hi, *ckv_lo, *ao_hi, *ao_lo;
    __nv_bfloat16 *Wqlr_hi, *Wqlr_lo, *Wqc_hi, *Wqc_lo, *Wqr_hi, *Wqr_lo;
    __nv_bfloat16 *Wkv_hi, *Wkv_lo, *Wkc_hi, *Wkc_lo, *Wv_hi, *Wv_lo, *Wo_hi, *Wo_lo;
    __nv_bfloat16 *Wkr_hi, *Wkr_lo, *qhi, *qlo, *khi, *klo, *vhi, *vlo;
    cudaGetSymbolAddress((void**)&h_hi,   g_h_hi);   cudaGetSymbolAddress((void**)&h_lo,   g_h_lo);
    cudaGetSymbolAddress((void**)&cq_hi,  g_cq_hi);  cudaGetSymbolAddress((void**)&cq_lo,  g_cq_lo);
    cudaGetSymbolAddress((void**)&ckv_hi, g_ckv_hi); cudaGetSymbolAddress((void**)&ckv_lo, g_ckv_lo);
    cudaGetSymbolAddress((void**)&ao_hi,  g_ao_hi);  cudaGetSymbolAddress((void**)&ao_lo,  g_ao_lo);
    cudaGetSymbolAddress((void**)&Wqlr_hi, g_Wqlr_hi); cudaGetSymbolAddress((void**)&Wqlr_lo, g_Wqlr_lo);
    cudaGetSymbolAddress((void**)&Wqc_hi,  g_Wqc_hi);  cudaGetSymbolAddress((void**)&Wqc_lo,  g_Wqc_lo);
    cudaGetSymbolAddress((void**)&Wqr_hi,  g_Wqr_hi);  cudaGetSymbolAddress((void**)&Wqr_lo,  g_Wqr_lo);
    cudaGetSymbolAddress((void**)&Wkv_hi,  g_Wkv_hi);  cudaGetSymbolAddress((void**)&Wkv_lo,  g_Wkv_lo);
    cudaGetSymbolAddress((void**)&Wkc_hi,  g_Wkc_hi);  cudaGetSymbolAddress((void**)&Wkc_lo,  g_Wkc_lo);
    cudaGetSymbolAddress((void**)&Wv_hi,   g_Wv_hi);   cudaGetSymbolAddress((void**)&Wv_lo,   g_Wv_lo);
    cudaGetSymbolAddress((void**)&Wo_hi,   g_Wo_hi);   cudaGetSymbolAddress((void**)&Wo_lo,   g_Wo_lo);
    cudaGetSymbolAddress((void**)&Wkr_hi,  g_Wkr_hi);  cudaGetSymbolAddress((void**)&Wkr_lo,  g_Wkr_lo);
    cudaGetSymbolAddress((void**)&qhi, g_qhi); cudaGetSymbolAddress((void**)&qlo, g_qlo);
    cudaGetSymbolAddress((void**)&khi, g_khi); cudaGetSymbolAddress((void**)&klo, g_klo);
    cudaGetSymbolAddress((void**)&vhi, g_vhi); cudaGetSymbolAddress((void**)&vlo, g_vlo);

    cudaFuncSetAttribute(mma_gemm6, cudaFuncAttributeMaxDynamicSharedMemorySize, G_SMEM);
    cudaFuncSetAttribute(attn_mma_kernel, cudaFuncAttributeMaxDynamicSharedMemorySize, ATT_SMEM);

    const int NONE = 0x7FFFFFFF;

    SJobs jobs;
    const float* srcs[8] = { hidden, Wq_lr, Wq_c, Wq_rope, Wkv, Wk_c, Wv, Wo };
    __nv_bfloat16* his[8] = { h_hi, Wqlr_hi, Wqc_hi, Wqr_hi, Wkv_hi, Wkc_hi, Wv_hi, Wo_hi };
    __nv_bfloat16* los[8] = { h_lo, Wqlr_lo, Wqc_lo, Wqr_lo, Wkv_lo, Wkc_lo, Wv_lo, Wo_lo };
    int ns[8] = { 2048*4096, 1536*4096, 4096*1536, 2048*1536,
                  512*4096, 4096*512, 4096*512, 4096*4096 };
    int blk = 0;
    for (int i = 0; i < 8; i++) {
        jobs.j[i].x = srcs[i]; jobs.j[i].hi = his[i]; jobs.j[i].lo = los[i];
        jobs.j[i].n8 = ns[i] / 8; jobs.j[i].blk0 = blk;
        blk += (jobs.j[i].n8 + 255) / 256;
    }
    multi_split_kernel<<<blk, 256>>>(jobs);
    pad_krope_kernel<<<(128 * 4096 + 255) / 256, 256>>>(Wk_rope, Wkr_hi, Wkr_lo, bk_rope, bkr);

    // G1: A = hidden (K=4096): c_q, c_kv, k_rope
    {
        GJobs g{};
        g.j[0] = { h_hi, h_lo, Wqlr_hi, Wqlr_lo, bq_lr, nullptr, cq_hi, cq_lo, 1536, 4096, 0, 0 };
        g.j[1] = { h_hi, h_lo, Wkv_hi,  Wkv_lo,  bkv,   nullptr, ckv_hi, ckv_lo, 512, 4096, 12, 0 };
        g.j[2] = { h_hi, h_lo, Wkr_hi,  Wkr_lo,  bkr,   kr, nullptr, nullptr, 128, 4096, 16, 0 };
        g.j[3] = g.j[2]; g.j[3].blk0 = NONE;
        mma_gemm6<<<dim3(17, 16), 128, G_SMEM>>>(g);
    }
    // G2+G3
    {
        GJobs g{};
        g.j[0] = { cq_hi, cq_lo, Wqc_hi, Wqc_lo, bq_c,    qc, nullptr, nullptr, 4096, 1536, 0,  0 };
        g.j[1] = { cq_hi, cq_lo, Wqr_hi, Wqr_lo, bq_rope, qr, nullptr, nullptr, 2048, 1536, 32, 0 };
        g.j[2] = { ckv_hi, ckv_lo, Wkc_hi, Wkc_lo, bk_c,  kc, nullptr, nullptr, 4096, 512, 48, 0 };
        g.j[3] = { ckv_hi, ckv_lo, Wv_hi,  Wv_lo,  bv, nullptr, vhi, vlo,       4096, 512, 80, 0 };
        mma_gemm6<<<dim3(112, 16), 128, G_SMEM>>>(g);
    }

    fuse_qk_kernel<<<16384, 256>>>(qc, qr, kc, kr, qhi, qlo, khi, klo);

    attn_mma_kernel<<<dim3(S_LEN / 64, NH), 128, ATT_SMEM>>>(
        qhi, qlo, khi, klo, vhi, vlo, mask, ao_hi, ao_lo);

    // G4: out = ao @ Wo^T
    {
        GJobs g{};
        g.j[0] = { ao_hi, ao_lo, Wo_hi, Wo_lo, bo, out, nullptr, nullptr, 4096, 4096, 0, 0 };
        g.j[1] = g.j[0]; g.j[1].blk0 = NONE;
        g.j[2] = g.j[0]; g.j[2].blk0 = NONE;
        g.j[3] = g.j[0]; g.j[3].blk0 = NONE;
        mma_gemm6<<<dim3(32, 16), 128, G_SMEM>>>(g);
    }
}